// round 8
// baseline (speedup 1.0000x reference)
#include <cuda_runtime.h>
#include <cuda_bf16.h>
#include <math.h>

// Problem constants
#define BATCH 2
#define NPTS  4096
#define NG    (BATCH*NPTS)     // 8192 nodes total
#define DIM   128
#define MDIM  16
#define KNN_K 32
#define EH    530              // edge hidden dim (2*265)
#define EHP   544              // padded to 17*32
#define NODE_IN 144            // DIM + MDIM
#define NODE_H  256
#define NPB   4                // nodes per edge-kernel block (1 warp each)

// -------------------- scratch (static device globals; no allocation) ----------
__device__ float d_A [NG * EHP];      // feats @ We1[0:128] + be1   (cols 530..543 stay 0)
__device__ float d_Bf[NG * EHP];      // feats @ We1[128:256]       (cols 530..543 stay 0)
__device__ int   d_idx[NG * KNN_K];
__device__ float d_mi [NG * MDIM];
__device__ float d_nodein[NG * NODE_IN];
__device__ float d_h  [NG * NODE_H];
__device__ float d_We2q[4 * EHP * 4]; // packed quads: [q][k][4]  (t = 4q..4q+3)
__device__ float d_W1fp[9 * EHP];     // zero-padded fourier rows of We1

__device__ __forceinline__ float siluf(float x) {
    return x / (1.0f + __expf(-x));
}

// ---------------- packed f32x2 helpers (Blackwell FFMA2 path) ------------------
__device__ __forceinline__ unsigned long long pk2(float lo, float hi) {
    unsigned long long r; asm("mov.b64 %0, {%1,%2};" : "=l"(r) : "f"(lo), "f"(hi)); return r;
}
__device__ __forceinline__ void upk2(unsigned long long v, float &lo, float &hi) {
    asm("mov.b64 {%0,%1}, %2;" : "=f"(lo), "=f"(hi) : "l"(v));
}
__device__ __forceinline__ unsigned long long fma2(unsigned long long a,
                                                   unsigned long long b,
                                                   unsigned long long c) {
    unsigned long long d;
    asm("fma.rn.f32x2 %0, %1, %2, %3;" : "=l"(d) : "l"(a), "l"(b), "l"(c));
    return d;
}
__device__ __forceinline__ unsigned long long add2(unsigned long long a,
                                                   unsigned long long b) {
    unsigned long long d;
    asm("add.rn.f32x2 %0, %1, %2;" : "=l"(d) : "l"(a), "l"(b));
    return d;
}

// ---------------------- build packed weight copies ------------------------------
__global__ void pad_weights_kernel(const float* __restrict__ We1,
                                   const float* __restrict__ We2)
{
    int i = blockIdx.x * blockDim.x + threadIdx.x;
    if (i < 4 * EHP * 4) {
        int q = i / (EHP * 4), r = i - q * (EHP * 4);
        int k = r >> 2, j = r & 3;
        d_We2q[i] = (k < EH) ? We2[k * 16 + q * 4 + j] : 0.f;
    }
    if (i < 9 * EHP) {
        int t = i / EHP, k = i - t * EHP;
        d_W1fp[i] = (k < EH) ? We1[(256 + t) * EH + k] : 0.f;
    }
}

// ------------------------------ KNN -------------------------------------------
__global__ __launch_bounds__(256) void knn_kernel(const float* __restrict__ coors)
{
    __shared__ unsigned long long keys[256];
    __shared__ unsigned long long swin;
    const int tid = threadIdx.x;
    const int g = blockIdx.x;
    const int boff = g & ~(NPTS - 1);

    const float cix = coors[g*3+0], ciy = coors[g*3+1], ciz = coors[g*3+2];

    float dv[16];
    #pragma unroll
    for (int s = 0; s < 16; s++) {
        const int j = tid + s*256;
        const int r = boff + j;
        float dx = cix - coors[r*3+0];
        float dy = ciy - coors[r*3+1];
        float dz = ciz - coors[r*3+2];
        dv[s] = dx*dx + dy*dy + dz*dz;
    }
    unsigned long long lb = 0xFFFFFFFFFFFFFFFFull;
    #pragma unroll
    for (int s = 0; s < 16; s++) {
        unsigned long long key =
            ((unsigned long long)__float_as_uint(dv[s]) << 32) | (unsigned)(tid + s*256);
        if (key < lb) lb = key;
    }

    for (int k = 0; k < KNN_K; k++) {
        keys[tid] = lb;
        __syncthreads();
        if (tid < 32) {
            unsigned long long v = keys[tid];
            #pragma unroll
            for (int o = 1; o < 8; o++) {
                unsigned long long t = keys[tid + o*32];
                if (t < v) v = t;
            }
            #pragma unroll
            for (int off = 16; off; off >>= 1) {
                unsigned long long o = __shfl_xor_sync(0xffffffffu, v, off);
                if (o < v) v = o;
            }
            if (tid == 0) {
                swin = v;
                d_idx[g*KNN_K + k] = (int)(v & 0xFFFFFFFFull);
            }
        }
        __syncthreads();
        const int wj = (int)(swin & 0xFFFFFFFFull);
        if ((wj & 255) == tid) {
            dv[wj >> 8] = __int_as_float(0x7F800000);
            lb = 0xFFFFFFFFFFFFFFFFull;
            #pragma unroll
            for (int s = 0; s < 16; s++) {
                unsigned long long key =
                    ((unsigned long long)__float_as_uint(dv[s]) << 32) | (unsigned)(tid + s*256);
                if (key < lb) lb = key;
            }
        }
    }
}

// ------------------------------ tiled GEMM 128x64 (FFMA2) ----------------------
__global__ __launch_bounds__(256) void gemm_k(
    const float* __restrict__ X, int ldx,
    const float* __restrict__ W, int ldw,
    const float* __restrict__ bias,
    const float* __restrict__ resid, int ldr,
    float* __restrict__ Y, int ldy,
    int M, int N, int K, int act)
{
    __shared__ float Xs[16*128];
    __shared__ float Ws[16*64];
    const int tid = threadIdx.x;
    const int tm = tid >> 4, tn = tid & 15;
    const int m0 = blockIdx.y * 128, n0 = blockIdx.x * 64;

    unsigned long long acc2[8][2];
    #pragma unroll
    for (int i = 0; i < 8; i++) { acc2[i][0] = 0ull; acc2[i][1] = 0ull; }

    for (int k0 = 0; k0 < K; k0 += 16) {
        #pragma unroll
        for (int i = 0; i < 8; i++) {
            int idx = tid + i*256;
            int m = idx >> 4, kk = idx & 15;
            Xs[kk*128 + (m ^ (kk*2))] = X[(size_t)(m0 + m) * ldx + k0 + kk];
        }
        #pragma unroll
        for (int i = 0; i < 4; i++) {
            int idx = tid + i*256;
            int kk = idx >> 6, n = idx & 63;
            int nn = n0 + n;
            Ws[kk*64 + n] = (nn < N) ? W[(size_t)(k0 + kk) * ldw + nn] : 0.f;
        }
        __syncthreads();
        #pragma unroll
        for (int kk = 0; kk < 16; kk++) {
            float a[8];
            #pragma unroll
            for (int i = 0; i < 8; i++) a[i] = Xs[kk*128 + ((tm*8 + i) ^ (kk*2))];
            float4 bv = *(const float4*)(Ws + kk*64 + tn*4);
            const unsigned long long bp0 = pk2(bv.x, bv.y);
            const unsigned long long bp1 = pk2(bv.z, bv.w);
            #pragma unroll
            for (int i = 0; i < 8; i++) {
                const unsigned long long ap = pk2(a[i], a[i]);
                acc2[i][0] = fma2(ap, bp0, acc2[i][0]);
                acc2[i][1] = fma2(ap, bp1, acc2[i][1]);
            }
        }
        __syncthreads();
    }

    #pragma unroll
    for (int i = 0; i < 8; i++) {
        int r = m0 + tm*8 + i;
        float vj[4];
        upk2(acc2[i][0], vj[0], vj[1]);
        upk2(acc2[i][1], vj[2], vj[3]);
        #pragma unroll
        for (int j = 0; j < 4; j++) {
            int c = n0 + tn*4 + j;
            if (c < N) {
                float v = vj[j];
                if (bias)  v += bias[c];
                if (act)   v = siluf(v);
                if (resid) v += resid[(size_t)r * ldr + c];
                Y[(size_t)r * ldy + c] = v;
            }
        }
    }
}

// ------------------------------ fused edge kernel ------------------------------
// 128 threads = 4 warps; 4 nodes/block; warp owns a node; 8 groups of 4 edges.
// All big weights (We2 quads, W1f, A-rows) fetched from global / L1-resident,
// lane-consecutive-k => coalesced. Smem only for tiny per-node data => 4 blocks/SM.
__global__ __launch_bounds__(128, 4) void edge_kernel(
    const float* __restrict__ coors,
    const float* __restrict__ be2,   // 16
    const float* __restrict__ Wc1,   // 16 x 64
    const float* __restrict__ bc1,   // 64
    const float* __restrict__ Wc2,   // 64
    const float* __restrict__ bc2,   // 1
    float* __restrict__ out_coors)   // NG x 3
{
    __shared__ float sWc1[16*64];
    __shared__ float sWc2[64];
    __shared__ float sbc1[64];
    __shared__ float sbe2[16];
    __shared__ float sfe[NPB*32*9];
    __shared__ float srel[NPB*32*3];
    __shared__ int   sj[NPB*32];

    const int tid  = threadIdx.x;
    const int w    = tid >> 5;
    const int lane = tid & 31;

    for (int i = tid; i < 1024; i += 128) sWc1[i] = Wc1[i];
    if (tid < 64) sWc2[tid] = Wc2[tid];
    if (tid < 64) sbc1[tid] = bc1[tid];
    if (tid < 16) sbe2[tid] = be2[tid];

    const int g = blockIdx.x * NPB + w;
    const int boff = g & ~(NPTS - 1);
    const float cix = coors[g*3+0], ciy = coors[g*3+1], ciz = coors[g*3+2];
    const float bc2v = bc2[0];

    // precompute all 32 edges' fourier features + rel coords (one lane each)
    {
        const int j = d_idx[g*KNN_K + lane];
        sj[w*32 + lane] = j;
        const int r = boff + j;
        float rx = cix - coors[r*3+0];
        float ry = ciy - coors[r*3+1];
        float rz = ciz - coors[r*3+2];
        float d  = rx*rx + ry*ry + rz*rz;
        float* fp = sfe + (w*32 + lane)*9;
        float s, c;
        sincosf(d,        &s, &c); fp[0] = s; fp[4] = c;
        sincosf(d*0.5f,   &s, &c); fp[1] = s; fp[5] = c;
        sincosf(d*0.25f,  &s, &c); fp[2] = s; fp[6] = c;
        sincosf(d*0.125f, &s, &c); fp[3] = s; fp[7] = c;
        fp[8] = d;
        float* rp = srel + (w*32 + lane)*3;
        rp[0] = rx; rp[1] = ry; rp[2] = rz;
    }
    __syncthreads();

    const int p  = lane & 7;          // pair index this lane will own after reduce
    const int eo = (lane >> 3) & 3;   // edge-in-group this lane will own
    unsigned long long misum_pack = 0ull;
    float cax = 0.f, cay = 0.f, caz = 0.f;

    const float* Ap = d_A + (size_t)g * EHP;
    const ulonglong2* wq = (const ulonglong2*)d_We2q;

    #pragma unroll 1
    for (int grp = 0; grp < 8; grp++) {
        const int e0 = grp*4;
        unsigned long long fe01[9], fe23[9];
        #pragma unroll
        for (int t = 0; t < 9; t++) {
            fe01[t] = pk2(sfe[(w*32 + e0    )*9 + t], sfe[(w*32 + e0 + 1)*9 + t]);
            fe23[t] = pk2(sfe[(w*32 + e0 + 2)*9 + t], sfe[(w*32 + e0 + 3)*9 + t]);
        }
        const float* B0 = d_Bf + (size_t)(boff + sj[w*32 + e0    ]) * EHP;
        const float* B1 = d_Bf + (size_t)(boff + sj[w*32 + e0 + 1]) * EHP;
        const float* B2 = d_Bf + (size_t)(boff + sj[w*32 + e0 + 2]) * EHP;
        const float* B3 = d_Bf + (size_t)(boff + sj[w*32 + e0 + 3]) * EHP;

        unsigned long long acc[4][8];
        #pragma unroll
        for (int e = 0; e < 4; e++)
            #pragma unroll
            for (int q = 0; q < 8; q++) acc[e][q] = 0ull;

        float b0 = B0[lane], b1 = B1[lane], b2 = B2[lane], b3 = B3[lane];

        #pragma unroll 1
        for (int it = 0; it < 17; it++) {
            const int k = it*32 + lane;
            float nb0, nb1, nb2, nb3;
            if (it < 16) {
                nb0 = B0[k + 32]; nb1 = B1[k + 32];
                nb2 = B2[k + 32]; nb3 = B3[k + 32];
            }
            const float a = __ldg(Ap + k);
            unsigned long long f01 = pk2(a + b0, a + b1);
            unsigned long long f23 = pk2(a + b2, a + b3);
            #pragma unroll
            for (int t = 0; t < 9; t++) {
                const float wv = __ldg(d_W1fp + t*EHP + k);
                const unsigned long long wp = pk2(wv, wv);
                f01 = fma2(fe01[t], wp, f01);
                f23 = fma2(fe23[t], wp, f23);
            }
            float f0, f1, f2, f3;
            upk2(f01, f0, f1); upk2(f23, f2, f3);
            unsigned long long hp[4];
            hp[0] = pk2(siluf(f0), siluf(f0));
            hp[1] = pk2(siluf(f1), siluf(f1));
            hp[2] = pk2(siluf(f2), siluf(f2));
            hp[3] = pk2(siluf(f3), siluf(f3));
            #pragma unroll
            for (int q = 0; q < 4; q++) {
                const ulonglong2 w2 = __ldg(wq + q*EHP + k);
                #pragma unroll
                for (int e = 0; e < 4; e++) {
                    acc[e][2*q]   = fma2(hp[e], w2.x, acc[e][2*q]);
                    acc[e][2*q+1] = fma2(hp[e], w2.y, acc[e][2*q+1]);
                }
            }
            b0 = nb0; b1 = nb1; b2 = nb2; b3 = nb3;
        }

        // reduce-scatter: lane L ends owning pair p=L&7 of edge (L>>3)&3
        unsigned long long r16[2][8];
        #pragma unroll
        for (int ee = 0; ee < 2; ee++)
            #pragma unroll
            for (int q = 0; q < 8; q++) {
                unsigned long long s = (lane & 16) ? acc[ee][q] : acc[ee+2][q];
                unsigned long long r = __shfl_xor_sync(0xffffffffu, s, 16);
                r16[ee][q] = add2((lane & 16) ? acc[ee+2][q] : acc[ee][q], r);
            }
        unsigned long long r8[8];
        #pragma unroll
        for (int q = 0; q < 8; q++) {
            unsigned long long s = (lane & 8) ? r16[0][q] : r16[1][q];
            unsigned long long r = __shfl_xor_sync(0xffffffffu, s, 8);
            r8[q] = add2((lane & 8) ? r16[1][q] : r16[0][q], r);
        }
        unsigned long long r4[4];
        #pragma unroll
        for (int q = 0; q < 4; q++) {
            unsigned long long s = (lane & 4) ? r8[q] : r8[q+4];
            unsigned long long r = __shfl_xor_sync(0xffffffffu, s, 4);
            r4[q] = add2((lane & 4) ? r8[q+4] : r8[q], r);
        }
        unsigned long long r2[2];
        #pragma unroll
        for (int q = 0; q < 2; q++) {
            unsigned long long s = (lane & 2) ? r4[q] : r4[q+2];
            unsigned long long r = __shfl_xor_sync(0xffffffffu, s, 2);
            r2[q] = add2((lane & 2) ? r4[q+2] : r4[q], r);
        }
        unsigned long long r1;
        {
            unsigned long long s = (lane & 1) ? r2[0] : r2[1];
            unsigned long long r = __shfl_xor_sync(0xffffffffu, s, 1);
            r1 = add2((lane & 1) ? r2[1] : r2[0], r);
        }

        float2 bp = *(const float2*)(sbe2 + 2*p);
        float lo, hi; upk2(r1, lo, hi);
        const float mlo = siluf(lo + bp.x);
        const float mhi = siluf(hi + bp.y);
        const unsigned long long mpack = pk2(mlo, mhi);
        misum_pack = add2(misum_pack, mpack);

        // rebuild full m[16] of own edge (8 u64 shfls)
        float mf[16];
        #pragma unroll
        for (int q = 0; q < 8; q++) {
            unsigned long long v = __shfl_sync(0xffffffffu, mpack, (lane & 24) | q);
            upk2(v, mf[2*q], mf[2*q+1]);
        }

        // coors MLP: lane handles 8 hidden cols [p*8, p*8+8) of its edge
        float4 hb0 = *(const float4*)(sbc1 + p*8);
        float4 hb1 = *(const float4*)(sbc1 + p*8 + 4);
        float h0 = hb0.x, h1 = hb0.y, h2 = hb0.z, h3 = hb0.w;
        float h4 = hb1.x, h5 = hb1.y, h6 = hb1.z, h7 = hb1.w;
        #pragma unroll
        for (int t = 0; t < MDIM; t++) {
            float4 wa = *(const float4*)(sWc1 + t*64 + p*8);
            float4 wb = *(const float4*)(sWc1 + t*64 + p*8 + 4);
            h0 = fmaf(mf[t], wa.x, h0); h1 = fmaf(mf[t], wa.y, h1);
            h2 = fmaf(mf[t], wa.z, h2); h3 = fmaf(mf[t], wa.w, h3);
            h4 = fmaf(mf[t], wb.x, h4); h5 = fmaf(mf[t], wb.y, h5);
            h6 = fmaf(mf[t], wb.z, h6); h7 = fmaf(mf[t], wb.w, h7);
        }
        float4 ca = *(const float4*)(sWc2 + p*8);
        float4 cb = *(const float4*)(sWc2 + p*8 + 4);
        float wv = siluf(h0)*ca.x + siluf(h1)*ca.y + siluf(h2)*ca.z + siluf(h3)*ca.w
                 + siluf(h4)*cb.x + siluf(h5)*cb.y + siluf(h6)*cb.z + siluf(h7)*cb.w;
        wv += __shfl_xor_sync(0xffffffffu, wv, 4);
        wv += __shfl_xor_sync(0xffffffffu, wv, 2);
        wv += __shfl_xor_sync(0xffffffffu, wv, 1);
        const float we = wv + bc2v;
        if (p == 0) {
            const float* rp = srel + (w*32 + e0 + eo)*3;
            cax = fmaf(we, rp[0], cax);
            cay = fmaf(we, rp[1], cay);
            caz = fmaf(we, rp[2], caz);
        }
    }

    // combine across edge groups (lanes 0,8,16,24 hold coords contributions)
    cax += __shfl_xor_sync(0xffffffffu, cax, 8);
    cax += __shfl_xor_sync(0xffffffffu, cax, 16);
    cay += __shfl_xor_sync(0xffffffffu, cay, 8);
    cay += __shfl_xor_sync(0xffffffffu, cay, 16);
    caz += __shfl_xor_sync(0xffffffffu, caz, 8);
    caz += __shfl_xor_sync(0xffffffffu, caz, 16);
    misum_pack = add2(misum_pack, __shfl_xor_sync(0xffffffffu, misum_pack, 8));
    misum_pack = add2(misum_pack, __shfl_xor_sync(0xffffffffu, misum_pack, 16));
    if (lane < 8) {
        float lo, hi; upk2(misum_pack, lo, hi);
        d_mi[(size_t)g*MDIM + 2*lane    ] = lo;
        d_mi[(size_t)g*MDIM + 2*lane + 1] = hi;
    }
    if (lane == 0) {
        out_coors[g*3+0] = cax + cix;
        out_coors[g*3+1] = cay + ciy;
        out_coors[g*3+2] = caz + ciz;
    }
}

// build concat(feats, m_i) -> d_nodein
__global__ void nodein_kernel(const float* __restrict__ feats)
{
    int i = blockIdx.x * blockDim.x + threadIdx.x;
    if (i < NG * NODE_IN) {
        int gg = i / NODE_IN, c = i - gg * NODE_IN;
        d_nodein[i] = (c < DIM) ? feats[(size_t)gg*DIM + c]
                                : d_mi[(size_t)gg*MDIM + (c - DIM)];
    }
}

// ------------------------------ launch ----------------------------------------
extern "C" void kernel_launch(void* const* d_in, const int* in_sizes, int n_in,
                              void* d_out, int out_size)
{
    const float* feats = (const float*)d_in[0];
    const float* coors = (const float*)d_in[1];
    const float* We1   = (const float*)d_in[2];
    const float* be1   = (const float*)d_in[3];
    const float* We2   = (const float*)d_in[4];
    const float* be2   = (const float*)d_in[5];
    const float* Wc1   = (const float*)d_in[6];
    const float* bc1   = (const float*)d_in[7];
    const float* Wc2   = (const float*)d_in[8];
    const float* bc2   = (const float*)d_in[9];
    const float* Wn1   = (const float*)d_in[10];
    const float* bn1   = (const float*)d_in[11];
    const float* Wn2   = (const float*)d_in[12];
    const float* bn2   = (const float*)d_in[13];

    float* out_nodes = (float*)d_out;
    float* out_coors = out_nodes + (size_t)NG * DIM;

    float *pA, *pB, *pNI, *pH;
    cudaGetSymbolAddress((void**)&pA,  d_A);
    cudaGetSymbolAddress((void**)&pB,  d_Bf);
    cudaGetSymbolAddress((void**)&pNI, d_nodein);
    cudaGetSymbolAddress((void**)&pH,  d_h);

    // 0. packed weight copies
    pad_weights_kernel<<<(4*EHP*4 + 255)/256, 256>>>(We1, We2);

    // 1. KNN
    knn_kernel<<<NG, 256>>>(coors);

    // 2. A = feats @ We1[0:128] + be1 ; B = feats @ We1[128:256]   (ld-out = 544)
    {
        dim3 grid((EH + 63) / 64, NG / 128);
        gemm_k<<<grid, 256>>>(feats, DIM, We1,          EH, be1,     nullptr, 0, pA, EHP, NG, EH, DIM, 0);
        gemm_k<<<grid, 256>>>(feats, DIM, We1 + 128*EH, EH, nullptr, nullptr, 0, pB, EHP, NG, EH, DIM, 0);
    }

    // 3. fused edge kernel: m_i + coors_out
    edge_kernel<<<NG / NPB, 128>>>(coors, be2, Wc1, bc1, Wc2, bc2, out_coors);

    // 4. node MLP
    nodein_kernel<<<(NG*NODE_IN + 255)/256, 256>>>(feats);
    {
        dim3 g1(NODE_H / 64, NG / 128);
        gemm_k<<<g1, 256>>>(pNI, NODE_IN, Wn1, NODE_H, bn1, nullptr, 0, pH, NODE_H, NG, NODE_H, NODE_IN, 1);
        dim3 g2(DIM / 64, NG / 128);
        gemm_k<<<g2, 256>>>(pH, NODE_H, Wn2, DIM, bn2, feats, DIM, out_nodes, DIM, NG, DIM, NODE_H, 0);
    }
}

// round 9
// speedup vs baseline: 1.3542x; 1.3542x over previous
#include <cuda_runtime.h>
#include <cuda_bf16.h>
#include <math.h>

// Problem constants
#define BATCH 2
#define NPTS  4096
#define NG    (BATCH*NPTS)     // 8192 nodes total
#define DIM   128
#define MDIM  16
#define KNN_K 32
#define EH    530              // edge hidden dim (2*265)
#define EHP   544              // padded to 17*32
#define NODE_IN 144            // DIM + MDIM
#define NODE_H  256
#define NPB   4                // nodes per edge-kernel block (1 warp each)

// -------------------- scratch (static device globals; no allocation) ----------
__device__ float d_A [NG * EHP];      // feats @ We1[0:128] + be1   (cols 530..543 stay 0)
__device__ float d_Bf[NG * EHP];      // feats @ We1[128:256]       (cols 530..543 stay 0)
__device__ int   d_idx[NG * KNN_K];
__device__ float d_mi [NG * MDIM];
__device__ float d_nodein[NG * NODE_IN];
__device__ float d_h  [NG * NODE_H];

__device__ __forceinline__ float siluf(float x) {
    return x / (1.0f + __expf(-x));
}

// ---------------- packed f32x2 helpers (Blackwell FFMA2 path) ------------------
__device__ __forceinline__ unsigned long long pk2(float lo, float hi) {
    unsigned long long r; asm("mov.b64 %0, {%1,%2};" : "=l"(r) : "f"(lo), "f"(hi)); return r;
}
__device__ __forceinline__ void upk2(unsigned long long v, float &lo, float &hi) {
    asm("mov.b64 {%0,%1}, %2;" : "=f"(lo), "=f"(hi) : "l"(v));
}
__device__ __forceinline__ unsigned long long fma2(unsigned long long a,
                                                   unsigned long long b,
                                                   unsigned long long c) {
    unsigned long long d;
    asm("fma.rn.f32x2 %0, %1, %2, %3;" : "=l"(d) : "l"(a), "l"(b), "l"(c));
    return d;
}
__device__ __forceinline__ unsigned long long add2(unsigned long long a,
                                                   unsigned long long b) {
    unsigned long long d;
    asm("add.rn.f32x2 %0, %1, %2;" : "=l"(d) : "l"(a), "l"(b));
    return d;
}

// ------------------------------ KNN -------------------------------------------
__global__ __launch_bounds__(256) void knn_kernel(const float* __restrict__ coors)
{
    __shared__ unsigned long long keys[256];
    __shared__ unsigned long long swin;
    const int tid = threadIdx.x;
    const int g = blockIdx.x;
    const int boff = g & ~(NPTS - 1);

    const float cix = coors[g*3+0], ciy = coors[g*3+1], ciz = coors[g*3+2];

    float dv[16];
    #pragma unroll
    for (int s = 0; s < 16; s++) {
        const int j = tid + s*256;
        const int r = boff + j;
        float dx = cix - coors[r*3+0];
        float dy = ciy - coors[r*3+1];
        float dz = ciz - coors[r*3+2];
        dv[s] = dx*dx + dy*dy + dz*dz;
    }
    unsigned long long lb = 0xFFFFFFFFFFFFFFFFull;
    #pragma unroll
    for (int s = 0; s < 16; s++) {
        unsigned long long key =
            ((unsigned long long)__float_as_uint(dv[s]) << 32) | (unsigned)(tid + s*256);
        if (key < lb) lb = key;
    }

    for (int k = 0; k < KNN_K; k++) {
        keys[tid] = lb;
        __syncthreads();
        if (tid < 32) {
            unsigned long long v = keys[tid];
            #pragma unroll
            for (int o = 1; o < 8; o++) {
                unsigned long long t = keys[tid + o*32];
                if (t < v) v = t;
            }
            #pragma unroll
            for (int off = 16; off; off >>= 1) {
                unsigned long long o = __shfl_xor_sync(0xffffffffu, v, off);
                if (o < v) v = o;
            }
            if (tid == 0) {
                swin = v;
                d_idx[g*KNN_K + k] = (int)(v & 0xFFFFFFFFull);
            }
        }
        __syncthreads();
        const int wj = (int)(swin & 0xFFFFFFFFull);
        if ((wj & 255) == tid) {
            dv[wj >> 8] = __int_as_float(0x7F800000);
            lb = 0xFFFFFFFFFFFFFFFFull;
            #pragma unroll
            for (int s = 0; s < 16; s++) {
                unsigned long long key =
                    ((unsigned long long)__float_as_uint(dv[s]) << 32) | (unsigned)(tid + s*256);
                if (key < lb) lb = key;
            }
        }
    }
}

// ------------------------ tiled GEMM 128x64 (FFMA2, M-pair packed) -------------
__global__ __launch_bounds__(256) void gemm_k(
    const float* __restrict__ X, int ldx,
    const float* __restrict__ W, int ldw,
    const float* __restrict__ bias,
    const float* __restrict__ resid, int ldr,
    float* __restrict__ Y, int ldy,
    int M, int N, int K, int act)
{
    __shared__ float Xs[16*128];
    __shared__ float Ws[16*64];
    const int tid = threadIdx.x;
    const int tm = tid >> 4, tn = tid & 15;
    const int m0 = blockIdx.y * 128, n0 = blockIdx.x * 64;

    // acc2[mp][j] = packed rows (tm*8+2mp, tm*8+2mp+1), col n0+tn*4+j
    unsigned long long acc2[4][4];
    #pragma unroll
    for (int mp = 0; mp < 4; mp++)
        #pragma unroll
        for (int j = 0; j < 4; j++) acc2[mp][j] = 0ull;

    for (int k0 = 0; k0 < K; k0 += 16) {
        #pragma unroll
        for (int i = 0; i < 8; i++) {
            int idx = tid + i*256;
            int m = idx >> 4, kk = idx & 15;
            Xs[kk*128 + (m ^ (kk*2))] = X[(size_t)(m0 + m) * ldx + k0 + kk];
        }
        #pragma unroll
        for (int i = 0; i < 4; i++) {
            int idx = tid + i*256;
            int kk = idx >> 6, n = idx & 63;
            int nn = n0 + n;
            Ws[kk*64 + n] = (nn < N) ? W[(size_t)(k0 + kk) * ldw + nn] : 0.f;
        }
        __syncthreads();
        #pragma unroll
        for (int kk = 0; kk < 16; kk++) {
            // natural M-pairs: (2mp)^(kk*2) is even and (2mp+1)^(kk*2) = it+1
            unsigned long long ap[4];
            #pragma unroll
            for (int mp = 0; mp < 4; mp++)
                ap[mp] = *(const unsigned long long*)&Xs[kk*128 + ((tm*8 + 2*mp) ^ (kk*2))];
            float4 bv = *(const float4*)(Ws + kk*64 + tn*4);
            unsigned long long bp[4];
            bp[0] = pk2(bv.x, bv.x); bp[1] = pk2(bv.y, bv.y);
            bp[2] = pk2(bv.z, bv.z); bp[3] = pk2(bv.w, bv.w);
            #pragma unroll
            for (int mp = 0; mp < 4; mp++)
                #pragma unroll
                for (int j = 0; j < 4; j++)
                    acc2[mp][j] = fma2(ap[mp], bp[j], acc2[mp][j]);
        }
        __syncthreads();
    }

    #pragma unroll
    for (int mp = 0; mp < 4; mp++) {
        float lo[4], hi[4];
        #pragma unroll
        for (int j = 0; j < 4; j++) upk2(acc2[mp][j], lo[j], hi[j]);
        const int r0 = m0 + tm*8 + 2*mp;
        #pragma unroll
        for (int j = 0; j < 4; j++) {
            int c = n0 + tn*4 + j;
            if (c < N) {
                float v0 = lo[j], v1 = hi[j];
                if (bias) { float b = bias[c]; v0 += b; v1 += b; }
                if (act)  { v0 = siluf(v0); v1 = siluf(v1); }
                if (resid) {
                    v0 += resid[(size_t)r0 * ldr + c];
                    v1 += resid[(size_t)(r0+1) * ldr + c];
                }
                Y[(size_t)r0 * ldy + c]     = v0;
                Y[(size_t)(r0+1) * ldy + c] = v1;
            }
        }
    }
}

// ------------------------------ fused edge kernel ------------------------------
// 128 threads = 4 warps; 4 nodes/block; warp owns a node; 8 groups of 4 edges.
__global__ __launch_bounds__(128, 3) void edge_kernel(
    const float* __restrict__ coors,
    const float* __restrict__ We1,   // 265 x 530 (rows 256..264 = fourier rows)
    const float* __restrict__ We2,   // 530 x 16
    const float* __restrict__ be2,   // 16
    const float* __restrict__ Wc1,   // 16 x 64
    const float* __restrict__ bc1,   // 64
    const float* __restrict__ Wc2,   // 64
    const float* __restrict__ bc2,   // 1
    float* __restrict__ out_coors)   // NG x 3
{
    extern __shared__ float sm[];
    float* sWe2P = sm;                       // ulonglong2[4][EHP] = 8704 floats
    float* sW1f  = sWe2P + 4*EHP*4;          // [9][EHP]
    float* sA    = sW1f  + 9*EHP;            // [NPB][EHP]
    float* sWc1  = sA    + NPB*EHP;          // [16][64]
    float* sWc2  = sWc1  + 1024;             // [64]
    float* sbc1  = sWc2  + 64;               // [64]
    float* sbe2  = sbc1  + 64;               // [16]
    float* sfe   = sbe2  + 16;               // [NPB][32][9]
    float* srel  = sfe   + NPB*32*9;         // [NPB][32][3]
    int*   sj    = (int*)(srel + NPB*32*3);  // [NPB][32]

    const int tid  = threadIdx.x;
    const int w    = tid >> 5;
    const int lane = tid & 31;

    // stage We2 as packed pair quads: entry (q,k) = {(t=4q,4q+1),(4q+2,4q+3)}
    for (int i = tid; i < 4*EHP*4; i += 128) {
        int q = i / (EHP*4), r = i - q*(EHP*4);
        int k = r >> 2, j = r & 3;
        sWe2P[(q*EHP + k)*4 + j] = (k < EH) ? We2[k*16 + q*4 + j] : 0.f;
    }
    for (int i = tid; i < 9*EHP; i += 128) {
        int t = i / EHP, k = i - t*EHP;
        sW1f[i] = (k < EH) ? We1[(256 + t)*EH + k] : 0.f;
    }
    {
        const int g0 = blockIdx.x * NPB;
        for (int i = tid; i < NPB*EHP; i += 128)
            sA[i] = d_A[(size_t)g0*EHP + i];
    }
    for (int i = tid; i < 1024; i += 128) sWc1[i] = Wc1[i];
    if (tid < 64) sWc2[tid] = Wc2[tid];
    if (tid < 64) sbc1[tid] = bc1[tid];
    if (tid < 16) sbe2[tid] = be2[tid];

    const int g = blockIdx.x * NPB + w;
    const int boff = g & ~(NPTS - 1);
    const float cix = coors[g*3+0], ciy = coors[g*3+1], ciz = coors[g*3+2];
    const float bc2v = bc2[0];

    // precompute all 32 edges' fourier features + rel coords (one lane each)
    {
        const int j = d_idx[g*KNN_K + lane];
        sj[w*32 + lane] = j;
        const int r = boff + j;
        float rx = cix - coors[r*3+0];
        float ry = ciy - coors[r*3+1];
        float rz = ciz - coors[r*3+2];
        float d  = rx*rx + ry*ry + rz*rz;
        float* fp = sfe + (w*32 + lane)*9;
        float s, c;
        sincosf(d,        &s, &c); fp[0] = s; fp[4] = c;
        sincosf(d*0.5f,   &s, &c); fp[1] = s; fp[5] = c;
        sincosf(d*0.25f,  &s, &c); fp[2] = s; fp[6] = c;
        sincosf(d*0.125f, &s, &c); fp[3] = s; fp[7] = c;
        fp[8] = d;
        float* rp = srel + (w*32 + lane)*3;
        rp[0] = rx; rp[1] = ry; rp[2] = rz;
    }
    __syncthreads();

    const int p  = lane & 7;          // pair index this lane will own after reduce
    const int eo = (lane >> 3) & 3;   // edge-in-group this lane will own
    unsigned long long misum_pack = 0ull;
    float cax = 0.f, cay = 0.f, caz = 0.f;

    #pragma unroll 1
    for (int grp = 0; grp < 8; grp++) {
        const int e0 = grp*4;
        unsigned long long fe01[9], fe23[9];
        #pragma unroll
        for (int t = 0; t < 9; t++) {
            fe01[t] = pk2(sfe[(w*32 + e0    )*9 + t], sfe[(w*32 + e0 + 1)*9 + t]);
            fe23[t] = pk2(sfe[(w*32 + e0 + 2)*9 + t], sfe[(w*32 + e0 + 3)*9 + t]);
        }
        const float* B0 = d_Bf + (size_t)(boff + sj[w*32 + e0    ]) * EHP;
        const float* B1 = d_Bf + (size_t)(boff + sj[w*32 + e0 + 1]) * EHP;
        const float* B2 = d_Bf + (size_t)(boff + sj[w*32 + e0 + 2]) * EHP;
        const float* B3 = d_Bf + (size_t)(boff + sj[w*32 + e0 + 3]) * EHP;

        unsigned long long acc[4][8];
        #pragma unroll
        for (int e = 0; e < 4; e++)
            #pragma unroll
            for (int q = 0; q < 8; q++) acc[e][q] = 0ull;

        float b0 = B0[lane], b1 = B1[lane], b2 = B2[lane], b3 = B3[lane];

        #pragma unroll 1
        for (int it = 0; it < 17; it++) {
            const int k = it*32 + lane;
            float nb0, nb1, nb2, nb3;
            if (it < 16) {
                nb0 = B0[k + 32]; nb1 = B1[k + 32];
                nb2 = B2[k + 32]; nb3 = B3[k + 32];
            }
            const float a = sA[w*EHP + k];
            unsigned long long f01 = pk2(a + b0, a + b1);
            unsigned long long f23 = pk2(a + b2, a + b3);
            #pragma unroll
            for (int t = 0; t < 9; t++) {
                const float wv = sW1f[t*EHP + k];
                const unsigned long long wp = pk2(wv, wv);
                f01 = fma2(fe01[t], wp, f01);
                f23 = fma2(fe23[t], wp, f23);
            }
            float f0, f1, f2, f3;
            upk2(f01, f0, f1); upk2(f23, f2, f3);
            unsigned long long hp[4];
            hp[0] = pk2(siluf(f0), siluf(f0));
            hp[1] = pk2(siluf(f1), siluf(f1));
            hp[2] = pk2(siluf(f2), siluf(f2));
            hp[3] = pk2(siluf(f3), siluf(f3));
            const ulonglong2* wq = (const ulonglong2*)sWe2P;
            #pragma unroll
            for (int q = 0; q < 4; q++) {
                ulonglong2 w2 = wq[q*EHP + k];
                #pragma unroll
                for (int e = 0; e < 4; e++) {
                    acc[e][2*q]   = fma2(hp[e], w2.x, acc[e][2*q]);
                    acc[e][2*q+1] = fma2(hp[e], w2.y, acc[e][2*q+1]);
                }
            }
            b0 = nb0; b1 = nb1; b2 = nb2; b3 = nb3;
        }

        // reduce-scatter: lane L ends owning pair p=L&7 of edge (L>>3)&3
        unsigned long long r16[2][8];
        #pragma unroll
        for (int ee = 0; ee < 2; ee++)
            #pragma unroll
            for (int q = 0; q < 8; q++) {
                unsigned long long s = (lane & 16) ? acc[ee][q] : acc[ee+2][q];
                unsigned long long r = __shfl_xor_sync(0xffffffffu, s, 16);
                r16[ee][q] = add2((lane & 16) ? acc[ee+2][q] : acc[ee][q], r);
            }
        unsigned long long r8[8];
        #pragma unroll
        for (int q = 0; q < 8; q++) {
            unsigned long long s = (lane & 8) ? r16[0][q] : r16[1][q];
            unsigned long long r = __shfl_xor_sync(0xffffffffu, s, 8);
            r8[q] = add2((lane & 8) ? r16[1][q] : r16[0][q], r);
        }
        unsigned long long r4[4];
        #pragma unroll
        for (int q = 0; q < 4; q++) {
            unsigned long long s = (lane & 4) ? r8[q] : r8[q+4];
            unsigned long long r = __shfl_xor_sync(0xffffffffu, s, 4);
            r4[q] = add2((lane & 4) ? r8[q+4] : r8[q], r);
        }
        unsigned long long r2[2];
        #pragma unroll
        for (int q = 0; q < 2; q++) {
            unsigned long long s = (lane & 2) ? r4[q] : r4[q+2];
            unsigned long long r = __shfl_xor_sync(0xffffffffu, s, 2);
            r2[q] = add2((lane & 2) ? r4[q+2] : r4[q], r);
        }
        unsigned long long r1;
        {
            unsigned long long s = (lane & 1) ? r2[0] : r2[1];
            unsigned long long r = __shfl_xor_sync(0xffffffffu, s, 1);
            r1 = add2((lane & 1) ? r2[1] : r2[0], r);
        }

        float2 bp = *(const float2*)(sbe2 + 2*p);
        float lo, hi; upk2(r1, lo, hi);
        const float mlo = siluf(lo + bp.x);
        const float mhi = siluf(hi + bp.y);
        const unsigned long long mpack = pk2(mlo, mhi);
        misum_pack = add2(misum_pack, mpack);

        // rebuild full m[16] of own edge (8 u64 shfls)
        float mf[16];
        #pragma unroll
        for (int q = 0; q < 8; q++) {
            unsigned long long v = __shfl_sync(0xffffffffu, mpack, (lane & 24) | q);
            upk2(v, mf[2*q], mf[2*q+1]);
        }

        // coors MLP: lane handles 8 hidden cols [p*8, p*8+8) of its edge
        float4 hb0 = *(const float4*)(sbc1 + p*8);
        float4 hb1 = *(const float4*)(sbc1 + p*8 + 4);
        float h0 = hb0.x, h1 = hb0.y, h2 = hb0.z, h3 = hb0.w;
        float h4 = hb1.x, h5 = hb1.y, h6 = hb1.z, h7 = hb1.w;
        #pragma unroll
        for (int t = 0; t < MDIM; t++) {
            float4 wa = *(const float4*)(sWc1 + t*64 + p*8);
            float4 wb = *(const float4*)(sWc1 + t*64 + p*8 + 4);
            h0 = fmaf(mf[t], wa.x, h0); h1 = fmaf(mf[t], wa.y, h1);
            h2 = fmaf(mf[t], wa.z, h2); h3 = fmaf(mf[t], wa.w, h3);
            h4 = fmaf(mf[t], wb.x, h4); h5 = fmaf(mf[t], wb.y, h5);
            h6 = fmaf(mf[t], wb.z, h6); h7 = fmaf(mf[t], wb.w, h7);
        }
        float4 ca = *(const float4*)(sWc2 + p*8);
        float4 cb = *(const float4*)(sWc2 + p*8 + 4);
        float wv = siluf(h0)*ca.x + siluf(h1)*ca.y + siluf(h2)*ca.z + siluf(h3)*ca.w
                 + siluf(h4)*cb.x + siluf(h5)*cb.y + siluf(h6)*cb.z + siluf(h7)*cb.w;
        wv += __shfl_xor_sync(0xffffffffu, wv, 4);
        wv += __shfl_xor_sync(0xffffffffu, wv, 2);
        wv += __shfl_xor_sync(0xffffffffu, wv, 1);
        const float we = wv + bc2v;
        if (p == 0) {
            const float* rp = srel + (w*32 + e0 + eo)*3;
            cax = fmaf(we, rp[0], cax);
            cay = fmaf(we, rp[1], cay);
            caz = fmaf(we, rp[2], caz);
        }
    }

    // combine across edge groups (lanes 0,8,16,24 hold coords contributions)
    cax += __shfl_xor_sync(0xffffffffu, cax, 8);
    cax += __shfl_xor_sync(0xffffffffu, cax, 16);
    cay += __shfl_xor_sync(0xffffffffu, cay, 8);
    cay += __shfl_xor_sync(0xffffffffu, cay, 16);
    caz += __shfl_xor_sync(0xffffffffu, caz, 8);
    caz += __shfl_xor_sync(0xffffffffu, caz, 16);
    misum_pack = add2(misum_pack, __shfl_xor_sync(0xffffffffu, misum_pack, 8));
    misum_pack = add2(misum_pack, __shfl_xor_sync(0xffffffffu, misum_pack, 16));
    if (lane < 8) {
        float lo, hi; upk2(misum_pack, lo, hi);
        d_mi[(size_t)g*MDIM + 2*lane    ] = lo;
        d_mi[(size_t)g*MDIM + 2*lane + 1] = hi;
    }
    if (lane == 0) {
        out_coors[g*3+0] = cax + cix;
        out_coors[g*3+1] = cay + ciy;
        out_coors[g*3+2] = caz + ciz;
    }
}

// build concat(feats, m_i) -> d_nodein
__global__ void nodein_kernel(const float* __restrict__ feats)
{
    int i = blockIdx.x * blockDim.x + threadIdx.x;
    if (i < NG * NODE_IN) {
        int gg = i / NODE_IN, c = i - gg * NODE_IN;
        d_nodein[i] = (c < DIM) ? feats[(size_t)gg*DIM + c]
                                : d_mi[(size_t)gg*MDIM + (c - DIM)];
    }
}

// ------------------------------ launch ----------------------------------------
extern "C" void kernel_launch(void* const* d_in, const int* in_sizes, int n_in,
                              void* d_out, int out_size)
{
    const float* feats = (const float*)d_in[0];
    const float* coors = (const float*)d_in[1];
    const float* We1   = (const float*)d_in[2];
    const float* be1   = (const float*)d_in[3];
    const float* We2   = (const float*)d_in[4];
    const float* be2   = (const float*)d_in[5];
    const float* Wc1   = (const float*)d_in[6];
    const float* bc1   = (const float*)d_in[7];
    const float* Wc2   = (const float*)d_in[8];
    const float* bc2   = (const float*)d_in[9];
    const float* Wn1   = (const float*)d_in[10];
    const float* bn1   = (const float*)d_in[11];
    const float* Wn2   = (const float*)d_in[12];
    const float* bn2   = (const float*)d_in[13];

    float* out_nodes = (float*)d_out;
    float* out_coors = out_nodes + (size_t)NG * DIM;

    float *pA, *pB, *pNI, *pH;
    cudaGetSymbolAddress((void**)&pA,  d_A);
    cudaGetSymbolAddress((void**)&pB,  d_Bf);
    cudaGetSymbolAddress((void**)&pNI, d_nodein);
    cudaGetSymbolAddress((void**)&pH,  d_h);

    const int smem_floats = 4*EHP*4 + 9*EHP + NPB*EHP + 1024 + 64 + 64 + 16
                          + NPB*32*9 + NPB*32*3 + NPB*32;
    const int smem_bytes  = smem_floats * 4;   // 74432
    cudaFuncSetAttribute(edge_kernel, cudaFuncAttributeMaxDynamicSharedMemorySize, smem_bytes);

    // 1. KNN
    knn_kernel<<<NG, 256>>>(coors);

    // 2. A = feats @ We1[0:128] + be1 ; B = feats @ We1[128:256]   (ld-out = 544)
    {
        dim3 grid((EH + 63) / 64, NG / 128);
        gemm_k<<<grid, 256>>>(feats, DIM, We1,          EH, be1,     nullptr, 0, pA, EHP, NG, EH, DIM, 0);
        gemm_k<<<grid, 256>>>(feats, DIM, We1 + 128*EH, EH, nullptr, nullptr, 0, pB, EHP, NG, EH, DIM, 0);
    }

    // 3. fused edge kernel: m_i + coors_out
    edge_kernel<<<NG / NPB, 128, smem_bytes>>>(coors, We1, We2, be2, Wc1, bc1, Wc2, bc2, out_coors);

    // 4. node MLP
    nodein_kernel<<<(NG*NODE_IN + 255)/256, 256>>>(feats);
    {
        dim3 g1(NODE_H / 64, NG / 128);
        gemm_k<<<g1, 256>>>(pNI, NODE_IN, Wn1, NODE_H, bn1, nullptr, 0, pH, NODE_H, NG, NODE_H, NODE_IN, 1);
        dim3 g2(DIM / 64, NG / 128);
        gemm_k<<<g2, 256>>>(pH, NODE_H, Wn2, DIM, bn2, feats, DIM, out_nodes, DIM, NG, DIM, NODE_H, 0);
    }
}

// round 10
// speedup vs baseline: 1.8549x; 1.3698x over previous
#include <cuda_runtime.h>
#include <cuda_bf16.h>
#include <math.h>

// Problem constants
#define BATCH 2
#define NPTS  4096
#define NG    (BATCH*NPTS)     // 8192 nodes total
#define DIM   128
#define MDIM  16
#define KNN_K 32
#define EH    530              // edge hidden dim (2*265)
#define EHP   544              // padded to 34*16
#define NSTEP 34               // k-tiles of 16
#define NODE_IN 144            // DIM + MDIM
#define NODE_H  256
#define NPB   4                // nodes per edge-kernel block (1 warp each)

// -------------------- scratch (static device globals; no allocation) ----------
__device__ float d_A [NG * EHP];      // feats @ We1[0:128] + be1   (cols 530..543 stay 0)
__device__ float d_Bf[NG * EHP];      // feats @ We1[128:256]       (cols 530..543 stay 0)
__device__ int   d_idx[NG * KNN_K];
__device__ float d_mi [NG * MDIM];
__device__ float d_nodein[NG * NODE_IN];
__device__ float d_h  [NG * NODE_H];
__device__ unsigned d_We2frag[NSTEP * 32 * 4];  // pre-packed bf16 B-fragments

__device__ __forceinline__ float siluf(float x) {
    return x / (1.0f + __expf(-x));
}
// fast silu for the bf16 hot path: x * sigmoid(x), sigmoid = 0.5*(1+tanh(x/2))
__device__ __forceinline__ float silu_fast(float x) {
    float xh = 0.5f * x;
    float t; asm("tanh.approx.f32 %0, %1;" : "=f"(t) : "f"(xh));
    return fmaf(xh, t, xh);
}

// ---------------- packed f32x2 helpers ------------------------------------------
__device__ __forceinline__ unsigned long long pk2(float lo, float hi) {
    unsigned long long r; asm("mov.b64 %0, {%1,%2};" : "=l"(r) : "f"(lo), "f"(hi)); return r;
}
__device__ __forceinline__ void upk2(unsigned long long v, float &lo, float &hi) {
    asm("mov.b64 {%0,%1}, %2;" : "=f"(lo), "=f"(hi) : "l"(v));
}
__device__ __forceinline__ unsigned long long fma2(unsigned long long a,
                                                   unsigned long long b,
                                                   unsigned long long c) {
    unsigned long long d;
    asm("fma.rn.f32x2 %0, %1, %2, %3;" : "=l"(d) : "l"(a), "l"(b), "l"(c));
    return d;
}
__device__ __forceinline__ unsigned long long add2(unsigned long long a,
                                                   unsigned long long b) {
    unsigned long long d;
    asm("add.rn.f32x2 %0, %1, %2;" : "=l"(d) : "l"(a), "l"(b));
    return d;
}
// bf16x2 pack: lo -> d[15:0], hi -> d[31:16]
__device__ __forceinline__ unsigned cvtbf2(float lo, float hi) {
    unsigned r; asm("cvt.rn.bf16x2.f32 %0, %1, %2;" : "=r"(r) : "f"(hi), "f"(lo)); return r;
}

#define MMA_BF16(d0,d1,d2,d3,a0,a1,a2,a3,b0,b1) \
    asm("mma.sync.aligned.m16n8k16.row.col.f32.bf16.bf16.f32 " \
        "{%0,%1,%2,%3},{%4,%5,%6,%7},{%8,%9},{%0,%1,%2,%3};" \
        : "+f"(d0),"+f"(d1),"+f"(d2),"+f"(d3) \
        : "r"(a0),"r"(a1),"r"(a2),"r"(a3),"r"(b0),"r"(b1))

// ---------------------- build packed We2 b-fragment table ----------------------
// Matrix-k permutation: cols {2q,2q+1} -> real k 16s+4q+{0,1}; {2q+8,2q+9} -> +{2,3}
__global__ void pad_weights_kernel(const float* __restrict__ We2)
{
    int i = blockIdx.x * blockDim.x + threadIdx.x;   // over NSTEP*32
    if (i < NSTEP * 32) {
        int s = i >> 5, l = i & 31;
        int q = l & 3, c0 = l >> 2;
        int k0 = s * 16 + q * 4;
        float v0 = (k0+0 < EH) ? We2[(k0+0)*16 + c0] : 0.f;
        float v1 = (k0+1 < EH) ? We2[(k0+1)*16 + c0] : 0.f;
        float v2 = (k0+2 < EH) ? We2[(k0+2)*16 + c0] : 0.f;
        float v3 = (k0+3 < EH) ? We2[(k0+3)*16 + c0] : 0.f;
        float w0 = (k0+0 < EH) ? We2[(k0+0)*16 + c0+8] : 0.f;
        float w1 = (k0+1 < EH) ? We2[(k0+1)*16 + c0+8] : 0.f;
        float w2 = (k0+2 < EH) ? We2[(k0+2)*16 + c0+8] : 0.f;
        float w3 = (k0+3 < EH) ? We2[(k0+3)*16 + c0+8] : 0.f;
        d_We2frag[i*4+0] = cvtbf2(v0, v1);
        d_We2frag[i*4+1] = cvtbf2(v2, v3);
        d_We2frag[i*4+2] = cvtbf2(w0, w1);
        d_We2frag[i*4+3] = cvtbf2(w2, w3);
    }
}

// ------------------------------ KNN -------------------------------------------
__global__ __launch_bounds__(256) void knn_kernel(const float* __restrict__ coors)
{
    __shared__ unsigned long long keys[256];
    __shared__ unsigned long long swin;
    const int tid = threadIdx.x;
    const int g = blockIdx.x;
    const int boff = g & ~(NPTS - 1);

    const float cix = coors[g*3+0], ciy = coors[g*3+1], ciz = coors[g*3+2];

    float dv[16];
    #pragma unroll
    for (int s = 0; s < 16; s++) {
        const int j = tid + s*256;
        const int r = boff + j;
        float dx = cix - coors[r*3+0];
        float dy = ciy - coors[r*3+1];
        float dz = ciz - coors[r*3+2];
        dv[s] = dx*dx + dy*dy + dz*dz;
    }
    unsigned long long lb = 0xFFFFFFFFFFFFFFFFull;
    #pragma unroll
    for (int s = 0; s < 16; s++) {
        unsigned long long key =
            ((unsigned long long)__float_as_uint(dv[s]) << 32) | (unsigned)(tid + s*256);
        if (key < lb) lb = key;
    }

    for (int k = 0; k < KNN_K; k++) {
        keys[tid] = lb;
        __syncthreads();
        if (tid < 32) {
            unsigned long long v = keys[tid];
            #pragma unroll
            for (int o = 1; o < 8; o++) {
                unsigned long long t = keys[tid + o*32];
                if (t < v) v = t;
            }
            #pragma unroll
            for (int off = 16; off; off >>= 1) {
                unsigned long long o = __shfl_xor_sync(0xffffffffu, v, off);
                if (o < v) v = o;
            }
            if (tid == 0) {
                swin = v;
                d_idx[g*KNN_K + k] = (int)(v & 0xFFFFFFFFull);
            }
        }
        __syncthreads();
        const int wj = (int)(swin & 0xFFFFFFFFull);
        if ((wj & 255) == tid) {
            dv[wj >> 8] = __int_as_float(0x7F800000);
            lb = 0xFFFFFFFFFFFFFFFFull;
            #pragma unroll
            for (int s = 0; s < 16; s++) {
                unsigned long long key =
                    ((unsigned long long)__float_as_uint(dv[s]) << 32) | (unsigned)(tid + s*256);
                if (key < lb) lb = key;
            }
        }
    }
}

// ------------------------ tiled GEMM 128x64 (FFMA2, M-pair packed) -------------
__global__ __launch_bounds__(256) void gemm_k(
    const float* __restrict__ X, int ldx,
    const float* __restrict__ W, int ldw,
    const float* __restrict__ bias,
    const float* __restrict__ resid, int ldr,
    float* __restrict__ Y, int ldy,
    int M, int N, int K, int act)
{
    __shared__ float Xs[16*128];
    __shared__ float Ws[16*64];
    const int tid = threadIdx.x;
    const int tm = tid >> 4, tn = tid & 15;
    const int m0 = blockIdx.y * 128, n0 = blockIdx.x * 64;

    unsigned long long acc2[4][4];
    #pragma unroll
    for (int mp = 0; mp < 4; mp++)
        #pragma unroll
        for (int j = 0; j < 4; j++) acc2[mp][j] = 0ull;

    for (int k0 = 0; k0 < K; k0 += 16) {
        #pragma unroll
        for (int i = 0; i < 8; i++) {
            int idx = tid + i*256;
            int m = idx >> 4, kk = idx & 15;
            Xs[kk*128 + (m ^ (kk*2))] = X[(size_t)(m0 + m) * ldx + k0 + kk];
        }
        #pragma unroll
        for (int i = 0; i < 4; i++) {
            int idx = tid + i*256;
            int kk = idx >> 6, n = idx & 63;
            int nn = n0 + n;
            Ws[kk*64 + n] = (nn < N) ? W[(size_t)(k0 + kk) * ldw + nn] : 0.f;
        }
        __syncthreads();
        #pragma unroll
        for (int kk = 0; kk < 16; kk++) {
            unsigned long long ap[4];
            #pragma unroll
            for (int mp = 0; mp < 4; mp++)
                ap[mp] = *(const unsigned long long*)&Xs[kk*128 + ((tm*8 + 2*mp) ^ (kk*2))];
            float4 bv = *(const float4*)(Ws + kk*64 + tn*4);
            unsigned long long bp[4];
            bp[0] = pk2(bv.x, bv.x); bp[1] = pk2(bv.y, bv.y);
            bp[2] = pk2(bv.z, bv.z); bp[3] = pk2(bv.w, bv.w);
            #pragma unroll
            for (int mp = 0; mp < 4; mp++)
                #pragma unroll
                for (int j = 0; j < 4; j++)
                    acc2[mp][j] = fma2(ap[mp], bp[j], acc2[mp][j]);
        }
        __syncthreads();
    }

    #pragma unroll
    for (int mp = 0; mp < 4; mp++) {
        float lo[4], hi[4];
        #pragma unroll
        for (int j = 0; j < 4; j++) upk2(acc2[mp][j], lo[j], hi[j]);
        const int r0 = m0 + tm*8 + 2*mp;
        #pragma unroll
        for (int j = 0; j < 4; j++) {
            int c = n0 + tn*4 + j;
            if (c < N) {
                float v0 = lo[j], v1 = hi[j];
                if (bias) { float b = bias[c]; v0 += b; v1 += b; }
                if (act)  { v0 = siluf(v0); v1 = siluf(v1); }
                if (resid) {
                    v0 += resid[(size_t)r0 * ldr + c];
                    v1 += resid[(size_t)(r0+1) * ldr + c];
                }
                Y[(size_t)r0 * ldy + c]     = v0;
                Y[(size_t)(r0+1) * ldy + c] = v1;
            }
        }
    }
}

// ------------------------------ fused edge kernel (mma.sync bf16) ---------------
// 128 threads = 4 warps; 4 nodes/block; warp owns a node; 2 groups of 16 edges.
// Layer-2 (530->16) done with m16n8k16 bf16 tensor-core mma, 2 n-tiles.
__global__ __launch_bounds__(128, 4) void edge_kernel(
    const float* __restrict__ coors,
    const float* __restrict__ We1,   // 265 x 530 (rows 256..264 = fourier rows)
    const float* __restrict__ be2,   // 16
    const float* __restrict__ Wc1,   // 16 x 64
    const float* __restrict__ bc1,   // 64
    const float* __restrict__ Wc2,   // 64
    const float* __restrict__ bc2,   // 1
    float* __restrict__ out_coors)   // NG x 3
{
    __shared__ __align__(16) float sW1f[9*EHP];     // fourier rows, zero-padded
    __shared__ __align__(16) float sA[NPB*EHP];
    __shared__ __align__(16) float sWc1[16*64];
    __shared__ float sWc2[64];
    __shared__ float sbc1[64];
    __shared__ float sbe2[16];
    __shared__ float sfe[NPB*32*9];
    __shared__ float srel[NPB*32*3];
    __shared__ float m_s[NPB*16*18];                // per-group m staging
    __shared__ int   sj[NPB*32];

    const int tid  = threadIdx.x;
    const int w    = tid >> 5;
    const int lane = tid & 31;

    for (int i = tid; i < 9*EHP; i += 128) {
        int t = i / EHP, k = i - t*EHP;
        sW1f[i] = (k < EH) ? We1[(256 + t)*EH + k] : 0.f;
    }
    {
        const int g0 = blockIdx.x * NPB;
        for (int i = tid; i < NPB*EHP; i += 128)
            sA[i] = d_A[(size_t)g0*EHP + i];
    }
    for (int i = tid; i < 1024; i += 128) sWc1[i] = Wc1[i];
    if (tid < 64) sWc2[tid] = Wc2[tid];
    if (tid < 64) sbc1[tid] = bc1[tid];
    if (tid < 16) sbe2[tid] = be2[tid];

    const int g = blockIdx.x * NPB + w;
    const int boff = g & ~(NPTS - 1);
    const float cix = coors[g*3+0], ciy = coors[g*3+1], ciz = coors[g*3+2];
    const float bc2v = bc2[0];

    // precompute all 32 edges' fourier features + rel coords (one lane each)
    {
        const int j = d_idx[g*KNN_K + lane];
        sj[w*32 + lane] = j;
        const int r = boff + j;
        float rx = cix - coors[r*3+0];
        float ry = ciy - coors[r*3+1];
        float rz = ciz - coors[r*3+2];
        float d  = rx*rx + ry*ry + rz*rz;
        float* fp = sfe + (w*32 + lane)*9;
        float s, c;
        sincosf(d,        &s, &c); fp[0] = s; fp[4] = c;
        sincosf(d*0.5f,   &s, &c); fp[1] = s; fp[5] = c;
        sincosf(d*0.25f,  &s, &c); fp[2] = s; fp[6] = c;
        sincosf(d*0.125f, &s, &c); fp[3] = s; fp[7] = c;
        fp[8] = d;
        float* rp = srel + (w*32 + lane)*3;
        rp[0] = rx; rp[1] = ry; rp[2] = rz;
    }
    __syncthreads();

    const int q  = lane & 3;          // fragment quad id
    const int E1 = lane >> 2;         // mma row (edge) 0..7
    const int E2 = E1 + 8;
    const int p  = lane & 7;          // coors-MLP col-octet
    const int eo = (lane >> 3) & 3;   // coors-MLP edge-in-subgroup
    float msum = 0.f;                 // lane<16: m_i component t=lane
    float cax = 0.f, cay = 0.f, caz = 0.f;

    #pragma unroll 1
    for (int grp = 0; grp < 2; grp++) {
        const int e0 = grp*16;
        // duplicated fourier features for this lane's two edges
        unsigned long long fe1d[9], fe2d[9];
        #pragma unroll
        for (int t = 0; t < 9; t++) {
            float v1 = sfe[(w*32 + e0 + E1)*9 + t];
            float v2 = sfe[(w*32 + e0 + E2)*9 + t];
            fe1d[t] = pk2(v1, v1);
            fe2d[t] = pk2(v2, v2);
        }
        const float* pB1 = d_Bf + (size_t)(boff + sj[w*32 + e0 + E1]) * EHP;
        const float* pB2 = d_Bf + (size_t)(boff + sj[w*32 + e0 + E2]) * EHP;

        float d00=0.f,d01=0.f,d02=0.f,d03=0.f;   // tile0 (t = 2q,2q+1)
        float u00=0.f,u01=0.f,u02=0.f,u03=0.f;   // tile1 (t = 2q+8,2q+9)

        ulonglong2 bb1 = *(const ulonglong2*)(pB1 + 4*q);
        ulonglong2 bb2 = *(const ulonglong2*)(pB2 + 4*q);

        #pragma unroll 1
        for (int s = 0; s < NSTEP; s++) {
            const int ka = s*16 + 4*q;
            ulonglong2 nb1, nb2;
            if (s < NSTEP-1) {
                nb1 = *(const ulonglong2*)(pB1 + ka + 16);
                nb2 = *(const ulonglong2*)(pB2 + ka + 16);
            }
            const ulonglong2 aa = *(const ulonglong2*)(sA + w*EHP + ka);
            unsigned long long f1a = add2(aa.x, bb1.x), f1b = add2(aa.y, bb1.y);
            unsigned long long f2a = add2(aa.x, bb2.x), f2b = add2(aa.y, bb2.y);
            #pragma unroll
            for (int t = 0; t < 9; t++) {
                const ulonglong2 wv = *(const ulonglong2*)(sW1f + t*EHP + ka);
                f1a = fma2(fe1d[t], wv.x, f1a);
                f1b = fma2(fe1d[t], wv.y, f1b);
                f2a = fma2(fe2d[t], wv.x, f2a);
                f2b = fma2(fe2d[t], wv.y, f2b);
            }
            float h0,h1,h2,h3,h4,h5,h6,h7;
            upk2(f1a, h0, h1); upk2(f1b, h2, h3);
            upk2(f2a, h4, h5); upk2(f2b, h6, h7);
            const unsigned a0 = cvtbf2(silu_fast(h0), silu_fast(h1));
            const unsigned a2 = cvtbf2(silu_fast(h2), silu_fast(h3));
            const unsigned a1 = cvtbf2(silu_fast(h4), silu_fast(h5));
            const unsigned a3 = cvtbf2(silu_fast(h6), silu_fast(h7));
            const uint4 bf = *(const uint4*)&d_We2frag[(s*32 + lane)*4];
            MMA_BF16(d00,d01,d02,d03, a0,a1,a2,a3, bf.x, bf.y);
            MMA_BF16(u00,u01,u02,u03, a0,a1,a2,a3, bf.z, bf.w);
            bb1 = nb1; bb2 = nb2;
        }

        // epilogue: m = silu(d + be2), stage to smem
        {
            const float b0 = sbe2[2*q], b1 = sbe2[2*q+1];
            const float b8 = sbe2[2*q+8], b9 = sbe2[2*q+9];
            float* mw = m_s + w*288;
            *(unsigned long long*)(mw + E1*18 + 2*q)     = pk2(siluf(d00+b0), siluf(d01+b1));
            *(unsigned long long*)(mw + E1*18 + 2*q + 8) = pk2(siluf(u00+b8), siluf(u01+b9));
            *(unsigned long long*)(mw + E2*18 + 2*q)     = pk2(siluf(d02+b0), siluf(d03+b1));
            *(unsigned long long*)(mw + E2*18 + 2*q + 8) = pk2(siluf(u02+b8), siluf(u03+b9));
        }
        __syncwarp();

        // m_i partial sums (lane < 16 meaningful; others harmless duplicates)
        {
            const float* mw = m_s + w*288 + (lane & 15);
            #pragma unroll
            for (int e = 0; e < 16; e++) msum += mw[e*18];
        }

        // coors MLP: 4 subpasses of 4 edges; 8 lanes per edge, 8 hidden cols each
        #pragma unroll 1
        for (int sub = 0; sub < 4; sub++) {
            const float* mrow = m_s + w*288 + (sub*4 + eo)*18;
            float mf[16];
            #pragma unroll
            for (int j = 0; j < 8; j++) {
                unsigned long long v = *(const unsigned long long*)(mrow + 2*j);
                upk2(v, mf[2*j], mf[2*j+1]);
            }
            float4 hb0 = *(const float4*)(sbc1 + p*8);
            float4 hb1 = *(const float4*)(sbc1 + p*8 + 4);
            float h0 = hb0.x, h1 = hb0.y, h2 = hb0.z, h3 = hb0.w;
            float h4 = hb1.x, h5 = hb1.y, h6 = hb1.z, h7 = hb1.w;
            #pragma unroll
            for (int t = 0; t < MDIM; t++) {
                float4 wa = *(const float4*)(sWc1 + t*64 + p*8);
                float4 wb = *(const float4*)(sWc1 + t*64 + p*8 + 4);
                h0 = fmaf(mf[t], wa.x, h0); h1 = fmaf(mf[t], wa.y, h1);
                h2 = fmaf(mf[t], wa.z, h2); h3 = fmaf(mf[t], wa.w, h3);
                h4 = fmaf(mf[t], wb.x, h4); h5 = fmaf(mf[t], wb.y, h5);
                h6 = fmaf(mf[t], wb.z, h6); h7 = fmaf(mf[t], wb.w, h7);
            }
            float4 ca = *(const float4*)(sWc2 + p*8);
            float4 cb = *(const float4*)(sWc2 + p*8 + 4);
            float wv = siluf(h0)*ca.x + siluf(h1)*ca.y + siluf(h2)*ca.z + siluf(h3)*ca.w
                     + siluf(h4)*cb.x + siluf(h5)*cb.y + siluf(h6)*cb.z + siluf(h7)*cb.w;
            wv += __shfl_xor_sync(0xffffffffu, wv, 4);
            wv += __shfl_xor_sync(0xffffffffu, wv, 2);
            wv += __shfl_xor_sync(0xffffffffu, wv, 1);
            const float we = wv + bc2v;
            if (p == 0) {
                const float* rp = srel + (w*32 + e0 + sub*4 + eo)*3;
                cax = fmaf(we, rp[0], cax);
                cay = fmaf(we, rp[1], cay);
                caz = fmaf(we, rp[2], caz);
            }
        }
        __syncwarp();
    }

    // combine (lanes 0,8,16,24 hold coords contributions)
    cax += __shfl_xor_sync(0xffffffffu, cax, 8);
    cax += __shfl_xor_sync(0xffffffffu, cax, 16);
    cay += __shfl_xor_sync(0xffffffffu, cay, 8);
    cay += __shfl_xor_sync(0xffffffffu, cay, 16);
    caz += __shfl_xor_sync(0xffffffffu, caz, 8);
    caz += __shfl_xor_sync(0xffffffffu, caz, 16);
    if (lane < 16) d_mi[(size_t)g*MDIM + lane] = msum;
    if (lane == 0) {
        out_coors[g*3+0] = cax + cix;
        out_coors[g*3+1] = cay + ciy;
        out_coors[g*3+2] = caz + ciz;
    }
}

// build concat(feats, m_i) -> d_nodein
__global__ void nodein_kernel(const float* __restrict__ feats)
{
    int i = blockIdx.x * blockDim.x + threadIdx.x;
    if (i < NG * NODE_IN) {
        int gg = i / NODE_IN, c = i - gg * NODE_IN;
        d_nodein[i] = (c < DIM) ? feats[(size_t)gg*DIM + c]
                                : d_mi[(size_t)gg*MDIM + (c - DIM)];
    }
}

// ------------------------------ launch ----------------------------------------
extern "C" void kernel_launch(void* const* d_in, const int* in_sizes, int n_in,
                              void* d_out, int out_size)
{
    const float* feats = (const float*)d_in[0];
    const float* coors = (const float*)d_in[1];
    const float* We1   = (const float*)d_in[2];
    const float* be1   = (const float*)d_in[3];
    const float* We2   = (const float*)d_in[4];
    const float* be2   = (const float*)d_in[5];
    const float* Wc1   = (const float*)d_in[6];
    const float* bc1   = (const float*)d_in[7];
    const float* Wc2   = (const float*)d_in[8];
    const float* bc2   = (const float*)d_in[9];
    const float* Wn1   = (const float*)d_in[10];
    const float* bn1   = (const float*)d_in[11];
    const float* Wn2   = (const float*)d_in[12];
    const float* bn2   = (const float*)d_in[13];

    float* out_nodes = (float*)d_out;
    float* out_coors = out_nodes + (size_t)NG * DIM;

    float *pA, *pB, *pNI, *pH;
    cudaGetSymbolAddress((void**)&pA,  d_A);
    cudaGetSymbolAddress((void**)&pB,  d_Bf);
    cudaGetSymbolAddress((void**)&pNI, d_nodein);
    cudaGetSymbolAddress((void**)&pH,  d_h);

    // 0. We2 b-fragment table
    pad_weights_kernel<<<(NSTEP*32 + 255)/256, 256>>>(We2);

    // 1. KNN
    knn_kernel<<<NG, 256>>>(coors);

    // 2. A = feats @ We1[0:128] + be1 ; B = feats @ We1[128:256]   (ld-out = 544)
    {
        dim3 grid((EH + 63) / 64, NG / 128);
        gemm_k<<<grid, 256>>>(feats, DIM, We1,          EH, be1,     nullptr, 0, pA, EHP, NG, EH, DIM, 0);
        gemm_k<<<grid, 256>>>(feats, DIM, We1 + 128*EH, EH, nullptr, nullptr, 0, pB, EHP, NG, EH, DIM, 0);
    }

    // 3. fused edge kernel: m_i + coors_out
    edge_kernel<<<NG / NPB, 128>>>(coors, We1, be2, Wc1, bc1, Wc2, bc2, out_coors);

    // 4. node MLP
    nodein_kernel<<<(NG*NODE_IN + 255)/256, 256>>>(feats);
    {
        dim3 g1(NODE_H / 64, NG / 128);
        gemm_k<<<g1, 256>>>(pNI, NODE_IN, Wn1, NODE_H, bn1, nullptr, 0, pH, NODE_H, NG, NODE_H, NODE_IN, 1);
        dim3 g2(DIM / 64, NG / 128);
        gemm_k<<<g2, 256>>>(pH, NODE_H, Wn2, DIM, bn2, feats, DIM, out_nodes, DIM, NG, DIM, NODE_H, 0);
    }
}

// round 11
// speedup vs baseline: 1.9905x; 1.0731x over previous
#include <cuda_runtime.h>
#include <cuda_bf16.h>
#include <math.h>

// Problem constants
#define BATCH 2
#define NPTS  4096
#define NG    (BATCH*NPTS)     // 8192 nodes total
#define DIM   128
#define MDIM  16
#define KNN_K 32
#define EH    530              // edge hidden dim (2*265)
#define EHP   544              // padded to 34*16
#define NSTEP 34               // k-tiles of 16
#define NODE_IN 144            // DIM + MDIM
#define NODE_H  256
#define NPB   4                // nodes per edge-kernel block (1 warp each)

// -------------------- scratch (static device globals; no allocation) ----------
__device__ float d_A [NG * EHP];      // feats @ We1[0:128] + be1   (cols 530..543 stay 0)
__device__ float d_Bf[NG * EHP];      // feats @ We1[128:256]       (cols 530..543 stay 0)
__device__ int   d_idx[NG * KNN_K];
__device__ float d_mi [NG * MDIM];
__device__ float d_nodein[NG * NODE_IN];
__device__ float d_h  [NG * NODE_H];
__device__ unsigned d_We2frag[NSTEP * 32 * 4];  // pre-packed bf16 B-fragments (layer 2)
__device__ unsigned d_W1ffrag[NSTEP * 32 * 4];  // pre-packed bf16 B-fragments (fourier layer 1)

__device__ __forceinline__ float siluf(float x) {
    return x / (1.0f + __expf(-x));
}
// fast silu: x * sigmoid(x), sigmoid = 0.5*(1+tanh(x/2))
__device__ __forceinline__ float silu_fast(float x) {
    float xh = 0.5f * x;
    float t; asm("tanh.approx.f32 %0, %1;" : "=f"(t) : "f"(xh));
    return fmaf(xh, t, xh);
}

// ---------------- packed f32x2 helpers ------------------------------------------
__device__ __forceinline__ unsigned long long pk2(float lo, float hi) {
    unsigned long long r; asm("mov.b64 %0, {%1,%2};" : "=l"(r) : "f"(lo), "f"(hi)); return r;
}
__device__ __forceinline__ void upk2(unsigned long long v, float &lo, float &hi) {
    asm("mov.b64 {%0,%1}, %2;" : "=f"(lo), "=f"(hi) : "l"(v));
}
__device__ __forceinline__ unsigned long long fma2(unsigned long long a,
                                                   unsigned long long b,
                                                   unsigned long long c) {
    unsigned long long d;
    asm("fma.rn.f32x2 %0, %1, %2, %3;" : "=l"(d) : "l"(a), "l"(b), "l"(c));
    return d;
}
__device__ __forceinline__ unsigned long long add2(unsigned long long a,
                                                   unsigned long long b) {
    unsigned long long d;
    asm("add.rn.f32x2 %0, %1, %2;" : "=l"(d) : "l"(a), "l"(b));
    return d;
}
// bf16x2 pack: lo -> d[15:0], hi -> d[31:16]
__device__ __forceinline__ unsigned cvtbf2(float lo, float hi) {
    unsigned r; asm("cvt.rn.bf16x2.f32 %0, %1, %2;" : "=r"(r) : "f"(hi), "f"(lo)); return r;
}

#define MMA_BF16(d0,d1,d2,d3,a0,a1,a2,a3,b0,b1) \
    asm("mma.sync.aligned.m16n8k16.row.col.f32.bf16.bf16.f32 " \
        "{%0,%1,%2,%3},{%4,%5,%6,%7},{%8,%9},{%0,%1,%2,%3};" \
        : "+f"(d0),"+f"(d1),"+f"(d2),"+f"(d3) \
        : "r"(a0),"r"(a1),"r"(a2),"r"(a3),"r"(b0),"r"(b1))

// ---------------------- build packed fragment tables ---------------------------
// k-permutation (both layers): matrix-k {2q,2q+1} <-> real 4q,4q+1 ;
//                              matrix-k {2q+8,2q+9} <-> real 4q+2,4q+3
// n-permutation (layer-1 D cols): tile0 col n -> real k 4*(n>>1)+(n&1); tile1 +2
__global__ void pad_weights_kernel(const float* __restrict__ We1,
                                   const float* __restrict__ We2)
{
    int i = blockIdx.x * blockDim.x + threadIdx.x;   // over NSTEP*32
    if (i < NSTEP * 32) {
        const int s = i >> 5, l = i & 31;
        const int q = l & 3, c0 = l >> 2;
        {   // We2 fragments (layer 2): n-col = c0 / c0+8, k chunk = s*16 + 4q..4q+3
            const int k0 = s * 16 + q * 4;
            float v0 = (k0+0 < EH) ? We2[(k0+0)*16 + c0] : 0.f;
            float v1 = (k0+1 < EH) ? We2[(k0+1)*16 + c0] : 0.f;
            float v2 = (k0+2 < EH) ? We2[(k0+2)*16 + c0] : 0.f;
            float v3 = (k0+3 < EH) ? We2[(k0+3)*16 + c0] : 0.f;
            float w0 = (k0+0 < EH) ? We2[(k0+0)*16 + c0+8] : 0.f;
            float w1 = (k0+1 < EH) ? We2[(k0+1)*16 + c0+8] : 0.f;
            float w2 = (k0+2 < EH) ? We2[(k0+2)*16 + c0+8] : 0.f;
            float w3 = (k0+3 < EH) ? We2[(k0+3)*16 + c0+8] : 0.f;
            d_We2frag[i*4+0] = cvtbf2(v0, v1);
            d_We2frag[i*4+1] = cvtbf2(v2, v3);
            d_We2frag[i*4+2] = cvtbf2(w0, w1);
            d_We2frag[i*4+3] = cvtbf2(w2, w3);
        }
        {   // W1f fragments (layer 1): fourier k-dim chunks 4q..4q+3 (f>=9 -> 0),
            // cols = real k offsets rk0 (tile0) / rk0+2 (tile1)
            const int rk0 = 4*(c0 >> 1) + (c0 & 1);
            const int ka = s*16 + rk0, kb = ka + 2;
            const int f0 = 4*q, f1 = 4*q+1, f2 = 4*q+2, f3 = 4*q+3;
            #define W1F(f,k) (((f) < 9 && (k) < EH) ? We1[(256+(f))*EH + (k)] : 0.f)
            d_W1ffrag[i*4+0] = cvtbf2(W1F(f0,ka), W1F(f1,ka));
            d_W1ffrag[i*4+1] = cvtbf2(W1F(f2,ka), W1F(f3,ka));
            d_W1ffrag[i*4+2] = cvtbf2(W1F(f0,kb), W1F(f1,kb));
            d_W1ffrag[i*4+3] = cvtbf2(W1F(f2,kb), W1F(f3,kb));
            #undef W1F
        }
    }
}

// ------------------------------ KNN -------------------------------------------
__global__ __launch_bounds__(256) void knn_kernel(const float* __restrict__ coors)
{
    __shared__ unsigned long long keys[256];
    __shared__ unsigned long long swin;
    const int tid = threadIdx.x;
    const int g = blockIdx.x;
    const int boff = g & ~(NPTS - 1);

    const float cix = coors[g*3+0], ciy = coors[g*3+1], ciz = coors[g*3+2];

    float dv[16];
    #pragma unroll
    for (int s = 0; s < 16; s++) {
        const int j = tid + s*256;
        const int r = boff + j;
        float dx = cix - coors[r*3+0];
        float dy = ciy - coors[r*3+1];
        float dz = ciz - coors[r*3+2];
        dv[s] = dx*dx + dy*dy + dz*dz;
    }
    unsigned long long lb = 0xFFFFFFFFFFFFFFFFull;
    #pragma unroll
    for (int s = 0; s < 16; s++) {
        unsigned long long key =
            ((unsigned long long)__float_as_uint(dv[s]) << 32) | (unsigned)(tid + s*256);
        if (key < lb) lb = key;
    }

    for (int k = 0; k < KNN_K; k++) {
        keys[tid] = lb;
        __syncthreads();
        if (tid < 32) {
            unsigned long long v = keys[tid];
            #pragma unroll
            for (int o = 1; o < 8; o++) {
                unsigned long long t = keys[tid + o*32];
                if (t < v) v = t;
            }
            #pragma unroll
            for (int off = 16; off; off >>= 1) {
                unsigned long long o = __shfl_xor_sync(0xffffffffu, v, off);
                if (o < v) v = o;
            }
            if (tid == 0) {
                swin = v;
                d_idx[g*KNN_K + k] = (int)(v & 0xFFFFFFFFull);
            }
        }
        __syncthreads();
        const int wj = (int)(swin & 0xFFFFFFFFull);
        if ((wj & 255) == tid) {
            dv[wj >> 8] = __int_as_float(0x7F800000);
            lb = 0xFFFFFFFFFFFFFFFFull;
            #pragma unroll
            for (int s = 0; s < 16; s++) {
                unsigned long long key =
                    ((unsigned long long)__float_as_uint(dv[s]) << 32) | (unsigned)(tid + s*256);
                if (key < lb) lb = key;
            }
        }
    }
}

// ------------------------ tiled GEMM 128x64 (FFMA2, M-pair packed) -------------
__global__ __launch_bounds__(256) void gemm_k(
    const float* __restrict__ X, int ldx,
    const float* __restrict__ W, int ldw,
    const float* __restrict__ bias,
    const float* __restrict__ resid, int ldr,
    float* __restrict__ Y, int ldy,
    int M, int N, int K, int act)
{
    __shared__ float Xs[16*128];
    __shared__ float Ws[16*64];
    const int tid = threadIdx.x;
    const int tm = tid >> 4, tn = tid & 15;
    const int m0 = blockIdx.y * 128, n0 = blockIdx.x * 64;

    unsigned long long acc2[4][4];
    #pragma unroll
    for (int mp = 0; mp < 4; mp++)
        #pragma unroll
        for (int j = 0; j < 4; j++) acc2[mp][j] = 0ull;

    for (int k0 = 0; k0 < K; k0 += 16) {
        #pragma unroll
        for (int i = 0; i < 8; i++) {
            int idx = tid + i*256;
            int m = idx >> 4, kk = idx & 15;
            Xs[kk*128 + (m ^ (kk*2))] = X[(size_t)(m0 + m) * ldx + k0 + kk];
        }
        #pragma unroll
        for (int i = 0; i < 4; i++) {
            int idx = tid + i*256;
            int kk = idx >> 6, n = idx & 63;
            int nn = n0 + n;
            Ws[kk*64 + n] = (nn < N) ? W[(size_t)(k0 + kk) * ldw + nn] : 0.f;
        }
        __syncthreads();
        #pragma unroll
        for (int kk = 0; kk < 16; kk++) {
            unsigned long long ap[4];
            #pragma unroll
            for (int mp = 0; mp < 4; mp++)
                ap[mp] = *(const unsigned long long*)&Xs[kk*128 + ((tm*8 + 2*mp) ^ (kk*2))];
            float4 bv = *(const float4*)(Ws + kk*64 + tn*4);
            unsigned long long bp[4];
            bp[0] = pk2(bv.x, bv.x); bp[1] = pk2(bv.y, bv.y);
            bp[2] = pk2(bv.z, bv.z); bp[3] = pk2(bv.w, bv.w);
            #pragma unroll
            for (int mp = 0; mp < 4; mp++)
                #pragma unroll
                for (int j = 0; j < 4; j++)
                    acc2[mp][j] = fma2(ap[mp], bp[j], acc2[mp][j]);
        }
        __syncthreads();
    }

    #pragma unroll
    for (int mp = 0; mp < 4; mp++) {
        float lo[4], hi[4];
        #pragma unroll
        for (int j = 0; j < 4; j++) upk2(acc2[mp][j], lo[j], hi[j]);
        const int r0 = m0 + tm*8 + 2*mp;
        #pragma unroll
        for (int j = 0; j < 4; j++) {
            int c = n0 + tn*4 + j;
            if (c < N) {
                float v0 = lo[j], v1 = hi[j];
                if (bias) { float b = bias[c]; v0 += b; v1 += b; }
                if (act)  { v0 = siluf(v0); v1 = siluf(v1); }
                if (resid) {
                    v0 += resid[(size_t)r0 * ldr + c];
                    v1 += resid[(size_t)(r0+1) * ldr + c];
                }
                Y[(size_t)r0 * ldy + c]     = v0;
                Y[(size_t)(r0+1) * ldy + c] = v1;
            }
        }
    }
}

// ------------------- fused edge kernel (dual mma.sync bf16) ---------------------
// 128 threads = 4 warps; 4 nodes/block; warp owns a node; 2 groups of 16 edges.
// Layer-1 fourier term AND layer-2 (530->16) on tensor cores; A+B stays fp32 via
// accumulator init. D-fragment of layer-1 == A-fragment of layer-2 by k-perm.
__global__ __launch_bounds__(128, 5) void edge_kernel(
    const float* __restrict__ coors,
    const float* __restrict__ be2,   // 16
    const float* __restrict__ Wc1,   // 16 x 64
    const float* __restrict__ bc1,   // 64
    const float* __restrict__ Wc2,   // 64
    const float* __restrict__ bc2,   // 1
    float* __restrict__ out_coors)   // NG x 3
{
    __shared__ __align__(16) float sA[NPB*EHP];
    __shared__ __align__(16) float sWc1[16*64];
    __shared__ float sWc2[64];
    __shared__ float sbc1[64];
    __shared__ float sbe2[16];
    __shared__ float sfe[NPB*32*9];
    __shared__ float srel[NPB*32*3];
    __shared__ float m_s[NPB*16*18];                // per-group m staging
    __shared__ int   sj[NPB*32];

    const int tid  = threadIdx.x;
    const int w    = tid >> 5;
    const int lane = tid & 31;

    {
        const int g0 = blockIdx.x * NPB;
        for (int i = tid; i < NPB*EHP; i += 128)
            sA[i] = d_A[(size_t)g0*EHP + i];
    }
    for (int i = tid; i < 1024; i += 128) sWc1[i] = Wc1[i];
    if (tid < 64) sWc2[tid] = Wc2[tid];
    if (tid < 64) sbc1[tid] = bc1[tid];
    if (tid < 16) sbe2[tid] = be2[tid];

    const int g = blockIdx.x * NPB + w;
    const int boff = g & ~(NPTS - 1);
    const float cix = coors[g*3+0], ciy = coors[g*3+1], ciz = coors[g*3+2];
    const float bc2v = bc2[0];

    // precompute all 32 edges' fourier features + rel coords (one lane each)
    {
        const int j = d_idx[g*KNN_K + lane];
        sj[w*32 + lane] = j;
        const int r = boff + j;
        float rx = cix - coors[r*3+0];
        float ry = ciy - coors[r*3+1];
        float rz = ciz - coors[r*3+2];
        float d  = rx*rx + ry*ry + rz*rz;
        float* fp = sfe + (w*32 + lane)*9;
        float s, c;
        sincosf(d,        &s, &c); fp[0] = s; fp[4] = c;
        sincosf(d*0.5f,   &s, &c); fp[1] = s; fp[5] = c;
        sincosf(d*0.25f,  &s, &c); fp[2] = s; fp[6] = c;
        sincosf(d*0.125f, &s, &c); fp[3] = s; fp[7] = c;
        fp[8] = d;
        float* rp = srel + (w*32 + lane)*3;
        rp[0] = rx; rp[1] = ry; rp[2] = rz;
    }
    __syncthreads();

    const int q  = lane & 3;          // fragment quad id
    const int E1 = lane >> 2;         // mma row (edge) 0..7
    const int E2 = E1 + 8;
    const int p  = lane & 7;          // coors-MLP col-octet
    const int eo = (lane >> 3) & 3;   // coors-MLP edge-in-subgroup
    float msum = 0.f;
    float cax = 0.f, cay = 0.f, caz = 0.f;

    #pragma unroll 1
    for (int grp = 0; grp < 2; grp++) {
        const int e0 = grp*16;
        // Fe A-fragment (fourier dim padded 9->16, same k-perm): built once per group
        unsigned feA0, feA1, feA2, feA3;
        {
            const float* f1 = sfe + (w*32 + e0 + E1)*9;
            const float* f2 = sfe + (w*32 + e0 + E2)*9;
            const int fq = 4*q;
            float a0 = (fq   < 9) ? f1[fq]   : 0.f;
            float a1 = (fq+1 < 9) ? f1[fq+1] : 0.f;
            float a2 = (fq+2 < 9) ? f1[fq+2] : 0.f;
            float a3 = (fq+3 < 9) ? f1[fq+3] : 0.f;
            float b0 = (fq   < 9) ? f2[fq]   : 0.f;
            float b1 = (fq+1 < 9) ? f2[fq+1] : 0.f;
            float b2 = (fq+2 < 9) ? f2[fq+2] : 0.f;
            float b3 = (fq+3 < 9) ? f2[fq+3] : 0.f;
            feA0 = cvtbf2(a0, a1);   // row E1, mat-f 2q,2q+1   (real 4q,4q+1)
            feA1 = cvtbf2(b0, b1);   // row E2
            feA2 = cvtbf2(a2, a3);   // row E1, mat-f 2q+8,2q+9 (real 4q+2,4q+3)
            feA3 = cvtbf2(b2, b3);   // row E2
        }
        const float* pB1 = d_Bf + (size_t)(boff + sj[w*32 + e0 + E1]) * EHP;
        const float* pB2 = d_Bf + (size_t)(boff + sj[w*32 + e0 + E2]) * EHP;

        float m00=0.f,m01=0.f,m02=0.f,m03=0.f;   // layer-2 acc tile0 (t=2q,2q+1)
        float m10=0.f,m11=0.f,m12=0.f,m13=0.f;   // layer-2 acc tile1 (t=2q+8,2q+9)

        ulonglong2 bb1 = *(const ulonglong2*)(pB1 + 4*q);
        ulonglong2 bb2 = *(const ulonglong2*)(pB2 + 4*q);

        #pragma unroll 1
        for (int s = 0; s < NSTEP; s++) {
            const int ka = s*16 + 4*q;
            ulonglong2 nb1, nb2;
            if (s < NSTEP-1) {
                nb1 = *(const ulonglong2*)(pB1 + ka + 16);
                nb2 = *(const ulonglong2*)(pB2 + ka + 16);
            }
            const ulonglong2 aa = *(const ulonglong2*)(sA + w*EHP + ka);
            // layer-1 accumulator init = fp32 A + B  (k 4q..4q+3, edges E1/E2)
            float d00,d01,d02,d03, u00,u01,u02,u03;
            { unsigned long long t = add2(aa.x, bb1.x); upk2(t, d00, d01); }
            { unsigned long long t = add2(aa.x, bb2.x); upk2(t, d02, d03); }
            { unsigned long long t = add2(aa.y, bb1.y); upk2(t, u00, u01); }
            { unsigned long long t = add2(aa.y, bb2.y); upk2(t, u02, u03); }
            // layer-1 fourier mma (h += Fe @ W1f)
            const uint4 wf = *(const uint4*)&d_W1ffrag[(s*32 + lane)*4];
            MMA_BF16(d00,d01,d02,d03, feA0,feA1,feA2,feA3, wf.x, wf.y);
            MMA_BF16(u00,u01,u02,u03, feA0,feA1,feA2,feA3, wf.z, wf.w);
            // silu + repack: D-frag(layer1) == A-frag(layer2)
            const unsigned a0 = cvtbf2(silu_fast(d00), silu_fast(d01));
            const unsigned a1 = cvtbf2(silu_fast(d02), silu_fast(d03));
            const unsigned a2 = cvtbf2(silu_fast(u00), silu_fast(u01));
            const unsigned a3 = cvtbf2(silu_fast(u02), silu_fast(u03));
            // layer-2 mma (m += h @ We2)
            const uint4 bf = *(const uint4*)&d_We2frag[(s*32 + lane)*4];
            MMA_BF16(m00,m01,m02,m03, a0,a1,a2,a3, bf.x, bf.y);
            MMA_BF16(m10,m11,m12,m13, a0,a1,a2,a3, bf.z, bf.w);
            bb1 = nb1; bb2 = nb2;
        }

        // epilogue: m = silu(m + be2), stage to smem
        {
            const float b0 = sbe2[2*q], b1 = sbe2[2*q+1];
            const float b8 = sbe2[2*q+8], b9 = sbe2[2*q+9];
            float* mw = m_s + w*288;
            *(unsigned long long*)(mw + E1*18 + 2*q)     = pk2(siluf(m00+b0), siluf(m01+b1));
            *(unsigned long long*)(mw + E1*18 + 2*q + 8) = pk2(siluf(m10+b8), siluf(m11+b9));
            *(unsigned long long*)(mw + E2*18 + 2*q)     = pk2(siluf(m02+b0), siluf(m03+b1));
            *(unsigned long long*)(mw + E2*18 + 2*q + 8) = pk2(siluf(m12+b8), siluf(m13+b9));
        }
        __syncwarp();

        // m_i partial sums
        {
            const float* mw = m_s + w*288 + (lane & 15);
            #pragma unroll
            for (int e = 0; e < 16; e++) msum += mw[e*18];
        }

        // coors MLP: 4 subpasses of 4 edges; 8 lanes per edge, 8 hidden cols each
        #pragma unroll 1
        for (int sub = 0; sub < 4; sub++) {
            const float* mrow = m_s + w*288 + (sub*4 + eo)*18;
            float mf[16];
            #pragma unroll
            for (int j = 0; j < 8; j++) {
                unsigned long long v = *(const unsigned long long*)(mrow + 2*j);
                upk2(v, mf[2*j], mf[2*j+1]);
            }
            float4 hb0 = *(const float4*)(sbc1 + p*8);
            float4 hb1 = *(const float4*)(sbc1 + p*8 + 4);
            float h0 = hb0.x, h1 = hb0.y, h2 = hb0.z, h3 = hb0.w;
            float h4 = hb1.x, h5 = hb1.y, h6 = hb1.z, h7 = hb1.w;
            #pragma unroll
            for (int t = 0; t < MDIM; t++) {
                float4 wa = *(const float4*)(sWc1 + t*64 + p*8);
                float4 wb = *(const float4*)(sWc1 + t*64 + p*8 + 4);
                h0 = fmaf(mf[t], wa.x, h0); h1 = fmaf(mf[t], wa.y, h1);
                h2 = fmaf(mf[t], wa.z, h2); h3 = fmaf(mf[t], wa.w, h3);
                h4 = fmaf(mf[t], wb.x, h4); h5 = fmaf(mf[t], wb.y, h5);
                h6 = fmaf(mf[t], wb.z, h6); h7 = fmaf(mf[t], wb.w, h7);
            }
            float4 ca = *(const float4*)(sWc2 + p*8);
            float4 cb = *(const float4*)(sWc2 + p*8 + 4);
            float wv = siluf(h0)*ca.x + siluf(h1)*ca.y + siluf(h2)*ca.z + siluf(h3)*ca.w
                     + siluf(h4)*cb.x + siluf(h5)*cb.y + siluf(h6)*cb.z + siluf(h7)*cb.w;
            wv += __shfl_xor_sync(0xffffffffu, wv, 4);
            wv += __shfl_xor_sync(0xffffffffu, wv, 2);
            wv += __shfl_xor_sync(0xffffffffu, wv, 1);
            const float we = wv + bc2v;
            if (p == 0) {
                const float* rp = srel + (w*32 + e0 + sub*4 + eo)*3;
                cax = fmaf(we, rp[0], cax);
                cay = fmaf(we, rp[1], cay);
                caz = fmaf(we, rp[2], caz);
            }
        }
        __syncwarp();
    }

    // combine (lanes 0,8,16,24 hold coords contributions)
    cax += __shfl_xor_sync(0xffffffffu, cax, 8);
    cax += __shfl_xor_sync(0xffffffffu, cax, 16);
    cay += __shfl_xor_sync(0xffffffffu, cay, 8);
    cay += __shfl_xor_sync(0xffffffffu, cay, 16);
    caz += __shfl_xor_sync(0xffffffffu, caz, 8);
    caz += __shfl_xor_sync(0xffffffffu, caz, 16);
    if (lane < 16) d_mi[(size_t)g*MDIM + lane] = msum;
    if (lane == 0) {
        out_coors[g*3+0] = cax + cix;
        out_coors[g*3+1] = cay + ciy;
        out_coors[g*3+2] = caz + ciz;
    }
}

// build concat(feats, m_i) -> d_nodein
__global__ void nodein_kernel(const float* __restrict__ feats)
{
    int i = blockIdx.x * blockDim.x + threadIdx.x;
    if (i < NG * NODE_IN) {
        int gg = i / NODE_IN, c = i - gg * NODE_IN;
        d_nodein[i] = (c < DIM) ? feats[(size_t)gg*DIM + c]
                                : d_mi[(size_t)gg*MDIM + (c - DIM)];
    }
}

// ------------------------------ launch ----------------------------------------
extern "C" void kernel_launch(void* const* d_in, const int* in_sizes, int n_in,
                              void* d_out, int out_size)
{
    const float* feats = (const float*)d_in[0];
    const float* coors = (const float*)d_in[1];
    const float* We1   = (const float*)d_in[2];
    const float* be1   = (const float*)d_in[3];
    const float* We2   = (const float*)d_in[4];
    const float* be2   = (const float*)d_in[5];
    const float* Wc1   = (const float*)d_in[6];
    const float* bc1   = (const float*)d_in[7];
    const float* Wc2   = (const float*)d_in[8];
    const float* bc2   = (const float*)d_in[9];
    const float* Wn1   = (const float*)d_in[10];
    const float* bn1   = (const float*)d_in[11];
    const float* Wn2   = (const float*)d_in[12];
    const float* bn2   = (const float*)d_in[13];

    float* out_nodes = (float*)d_out;
    float* out_coors = out_nodes + (size_t)NG * DIM;

    float *pA, *pB, *pNI, *pH;
    cudaGetSymbolAddress((void**)&pA,  d_A);
    cudaGetSymbolAddress((void**)&pB,  d_Bf);
    cudaGetSymbolAddress((void**)&pNI, d_nodein);
    cudaGetSymbolAddress((void**)&pH,  d_h);

    // 0. fragment tables
    pad_weights_kernel<<<(NSTEP*32 + 255)/256, 256>>>(We1, We2);

    // 1. KNN
    knn_kernel<<<NG, 256>>>(coors);

    // 2. A = feats @ We1[0:128] + be1 ; B = feats @ We1[128:256]   (ld-out = 544)
    {
        dim3 grid((EH + 63) / 64, NG / 128);
        gemm_k<<<grid, 256>>>(feats, DIM, We1,          EH, be1,     nullptr, 0, pA, EHP, NG, EH, DIM, 0);
        gemm_k<<<grid, 256>>>(feats, DIM, We1 + 128*EH, EH, nullptr, nullptr, 0, pB, EHP, NG, EH, DIM, 0);
    }

    // 3. fused edge kernel: m_i + coors_out
    edge_kernel<<<NG / NPB, 128>>>(coors, be2, Wc1, bc1, Wc2, bc2, out_coors);

    // 4. node MLP
    nodein_kernel<<<(NG*NODE_IN + 255)/256, 256>>>(feats);
    {
        dim3 g1(NODE_H / 64, NG / 128);
        gemm_k<<<g1, 256>>>(pNI, NODE_IN, Wn1, NODE_H, bn1, nullptr, 0, pH, NODE_H, NG, NODE_H, NODE_IN, 1);
        dim3 g2(DIM / 64, NG / 128);
        gemm_k<<<g2, 256>>>(pH, NODE_H, Wn2, DIM, bn2, feats, DIM, out_nodes, DIM, NG, DIM, NODE_H, 0);
    }
}

// round 12
// speedup vs baseline: 2.6729x; 1.3428x over previous
#include <cuda_runtime.h>
#include <cuda_bf16.h>
#include <math.h>

// Problem constants
#define BATCH 2
#define NPTS  4096
#define NG    (BATCH*NPTS)     // 8192 nodes total
#define DIM   128
#define MDIM  16
#define KNN_K 32
#define EH    530              // edge hidden dim (2*265)
#define EHP   544              // padded to 34*16
#define NSTEP 34               // k-tiles of 16
#define NODE_IN 144            // DIM + MDIM
#define NODE_H  256
#define NPB   4                // nodes per edge-kernel block (1 warp each)

// -------------------- scratch (static device globals; no allocation) ----------
__device__ float d_A [NG * EHP];      // feats @ We1[0:128] + be1   (cols 530..543 stay 0)
__device__ float d_Bf[NG * EHP];      // feats @ We1[128:256]       (cols 530..543 stay 0)
__device__ int   d_idx[NG * KNN_K];
__device__ float d_mi [NG * MDIM];
__device__ float d_nodein[NG * NODE_IN];
__device__ float d_h  [NG * NODE_H];
__device__ unsigned d_We2frag[NSTEP * 32 * 4];  // bf16 B-fragments (layer 2)
__device__ unsigned d_W1ffrag[NSTEP * 32 * 4];  // bf16 B-fragments (fourier layer 1)
__device__ uint2    d_Wc1frag[8 * 32];          // bf16 B-fragments (coors layer 1)

__device__ __forceinline__ float siluf(float x) {
    return x / (1.0f + __expf(-x));
}
// fast silu: x * sigmoid(x), sigmoid = 0.5*(1+tanh(x/2))
__device__ __forceinline__ float silu_fast(float x) {
    float xh = 0.5f * x;
    float t; asm("tanh.approx.f32 %0, %1;" : "=f"(t) : "f"(xh));
    return fmaf(xh, t, xh);
}

// ---------------- packed f32x2 helpers ------------------------------------------
__device__ __forceinline__ unsigned long long pk2(float lo, float hi) {
    unsigned long long r; asm("mov.b64 %0, {%1,%2};" : "=l"(r) : "f"(lo), "f"(hi)); return r;
}
__device__ __forceinline__ void upk2(unsigned long long v, float &lo, float &hi) {
    asm("mov.b64 {%0,%1}, %2;" : "=f"(lo), "=f"(hi) : "l"(v));
}
__device__ __forceinline__ unsigned long long fma2(unsigned long long a,
                                                   unsigned long long b,
                                                   unsigned long long c) {
    unsigned long long d;
    asm("fma.rn.f32x2 %0, %1, %2, %3;" : "=l"(d) : "l"(a), "l"(b), "l"(c));
    return d;
}
__device__ __forceinline__ unsigned long long add2(unsigned long long a,
                                                   unsigned long long b) {
    unsigned long long d;
    asm("add.rn.f32x2 %0, %1, %2;" : "=l"(d) : "l"(a), "l"(b));
    return d;
}
// bf16x2 pack: lo -> d[15:0], hi -> d[31:16]
__device__ __forceinline__ unsigned cvtbf2(float lo, float hi) {
    unsigned r; asm("cvt.rn.bf16x2.f32 %0, %1, %2;" : "=r"(r) : "f"(hi), "f"(lo)); return r;
}

#define MMA_BF16(d0,d1,d2,d3,a0,a1,a2,a3,b0,b1) \
    asm("mma.sync.aligned.m16n8k16.row.col.f32.bf16.bf16.f32 " \
        "{%0,%1,%2,%3},{%4,%5,%6,%7},{%8,%9},{%0,%1,%2,%3};" \
        : "+f"(d0),"+f"(d1),"+f"(d2),"+f"(d3) \
        : "r"(a0),"r"(a1),"r"(a2),"r"(a3),"r"(b0),"r"(b1))

// ---------------------- build packed fragment tables ---------------------------
__global__ void pad_weights_kernel(const float* __restrict__ We1,
                                   const float* __restrict__ We2,
                                   const float* __restrict__ Wc1)
{
    int i = blockIdx.x * blockDim.x + threadIdx.x;   // over NSTEP*32
    if (i < NSTEP * 32) {
        const int s = i >> 5, l = i & 31;
        const int q = l & 3, c0 = l >> 2;
        {   // We2 fragments (layer 2)
            const int k0 = s * 16 + q * 4;
            float v0 = (k0+0 < EH) ? We2[(k0+0)*16 + c0] : 0.f;
            float v1 = (k0+1 < EH) ? We2[(k0+1)*16 + c0] : 0.f;
            float v2 = (k0+2 < EH) ? We2[(k0+2)*16 + c0] : 0.f;
            float v3 = (k0+3 < EH) ? We2[(k0+3)*16 + c0] : 0.f;
            float w0 = (k0+0 < EH) ? We2[(k0+0)*16 + c0+8] : 0.f;
            float w1 = (k0+1 < EH) ? We2[(k0+1)*16 + c0+8] : 0.f;
            float w2 = (k0+2 < EH) ? We2[(k0+2)*16 + c0+8] : 0.f;
            float w3 = (k0+3 < EH) ? We2[(k0+3)*16 + c0+8] : 0.f;
            d_We2frag[i*4+0] = cvtbf2(v0, v1);
            d_We2frag[i*4+1] = cvtbf2(v2, v3);
            d_We2frag[i*4+2] = cvtbf2(w0, w1);
            d_We2frag[i*4+3] = cvtbf2(w2, w3);
        }
        {   // W1f fragments (layer 1)
            const int rk0 = 4*(c0 >> 1) + (c0 & 1);
            const int ka = s*16 + rk0, kb = ka + 2;
            const int f0 = 4*q, f1 = 4*q+1, f2 = 4*q+2, f3 = 4*q+3;
            #define W1F(f,k) (((f) < 9 && (k) < EH) ? We1[(256+(f))*EH + (k)] : 0.f)
            d_W1ffrag[i*4+0] = cvtbf2(W1F(f0,ka), W1F(f1,ka));
            d_W1ffrag[i*4+1] = cvtbf2(W1F(f2,ka), W1F(f3,ka));
            d_W1ffrag[i*4+2] = cvtbf2(W1F(f0,kb), W1F(f1,kb));
            d_W1ffrag[i*4+3] = cvtbf2(W1F(f2,kb), W1F(f3,kb));
            #undef W1F
        }
    }
    // Wc1 fragments (coors layer 1): identity k-map, 8 n-tiles of 8 cols.
    if (i < 8 * 32) {
        const int nt = i >> 5, l = i & 31;
        const int q = l & 3, c = l >> 2;
        const int col = nt*8 + c;
        d_Wc1frag[i].x = cvtbf2(Wc1[(2*q  )*64 + col], Wc1[(2*q+1)*64 + col]);
        d_Wc1frag[i].y = cvtbf2(Wc1[(2*q+8)*64 + col], Wc1[(2*q+9)*64 + col]);
    }
}

// ------------------------------ KNN -------------------------------------------
__global__ __launch_bounds__(256) void knn_kernel(const float* __restrict__ coors)
{
    __shared__ unsigned long long keys[256];
    __shared__ unsigned long long swin;
    const int tid = threadIdx.x;
    const int g = blockIdx.x;
    const int boff = g & ~(NPTS - 1);

    const float cix = coors[g*3+0], ciy = coors[g*3+1], ciz = coors[g*3+2];

    float dv[16];
    #pragma unroll
    for (int s = 0; s < 16; s++) {
        const int j = tid + s*256;
        const int r = boff + j;
        float dx = cix - coors[r*3+0];
        float dy = ciy - coors[r*3+1];
        float dz = ciz - coors[r*3+2];
        dv[s] = dx*dx + dy*dy + dz*dz;
    }
    unsigned long long lb = 0xFFFFFFFFFFFFFFFFull;
    #pragma unroll
    for (int s = 0; s < 16; s++) {
        unsigned long long key =
            ((unsigned long long)__float_as_uint(dv[s]) << 32) | (unsigned)(tid + s*256);
        if (key < lb) lb = key;
    }

    for (int k = 0; k < KNN_K; k++) {
        keys[tid] = lb;
        __syncthreads();
        if (tid < 32) {
            unsigned long long v = keys[tid];
            #pragma unroll
            for (int o = 1; o < 8; o++) {
                unsigned long long t = keys[tid + o*32];
                if (t < v) v = t;
            }
            #pragma unroll
            for (int off = 16; off; off >>= 1) {
                unsigned long long o = __shfl_xor_sync(0xffffffffu, v, off);
                if (o < v) v = o;
            }
            if (tid == 0) {
                swin = v;
                d_idx[g*KNN_K + k] = (int)(v & 0xFFFFFFFFull);
            }
        }
        __syncthreads();
        const int wj = (int)(swin & 0xFFFFFFFFull);
        if ((wj & 255) == tid) {
            dv[wj >> 8] = __int_as_float(0x7F800000);
            lb = 0xFFFFFFFFFFFFFFFFull;
            #pragma unroll
            for (int s = 0; s < 16; s++) {
                unsigned long long key =
                    ((unsigned long long)__float_as_uint(dv[s]) << 32) | (unsigned)(tid + s*256);
                if (key < lb) lb = key;
            }
        }
    }
}

// ------------------------ tiled GEMM 128x64 (FFMA2, M-pair packed) -------------
__global__ __launch_bounds__(256) void gemm_k(
    const float* __restrict__ X, int ldx,
    const float* __restrict__ W, int ldw,
    const float* __restrict__ bias,
    const float* __restrict__ resid, int ldr,
    float* __restrict__ Y, int ldy,
    int M, int N, int K, int act)
{
    __shared__ float Xs[16*128];
    __shared__ float Ws[16*64];
    const int tid = threadIdx.x;
    const int tm = tid >> 4, tn = tid & 15;
    const int m0 = blockIdx.y * 128, n0 = blockIdx.x * 64;

    unsigned long long acc2[4][4];
    #pragma unroll
    for (int mp = 0; mp < 4; mp++)
        #pragma unroll
        for (int j = 0; j < 4; j++) acc2[mp][j] = 0ull;

    for (int k0 = 0; k0 < K; k0 += 16) {
        #pragma unroll
        for (int i = 0; i < 8; i++) {
            int idx = tid + i*256;
            int m = idx >> 4, kk = idx & 15;
            Xs[kk*128 + (m ^ (kk*2))] = X[(size_t)(m0 + m) * ldx + k0 + kk];
        }
        #pragma unroll
        for (int i = 0; i < 4; i++) {
            int idx = tid + i*256;
            int kk = idx >> 6, n = idx & 63;
            int nn = n0 + n;
            Ws[kk*64 + n] = (nn < N) ? W[(size_t)(k0 + kk) * ldw + nn] : 0.f;
        }
        __syncthreads();
        #pragma unroll
        for (int kk = 0; kk < 16; kk++) {
            unsigned long long ap[4];
            #pragma unroll
            for (int mp = 0; mp < 4; mp++)
                ap[mp] = *(const unsigned long long*)&Xs[kk*128 + ((tm*8 + 2*mp) ^ (kk*2))];
            float4 bv = *(const float4*)(Ws + kk*64 + tn*4);
            unsigned long long bp[4];
            bp[0] = pk2(bv.x, bv.x); bp[1] = pk2(bv.y, bv.y);
            bp[2] = pk2(bv.z, bv.z); bp[3] = pk2(bv.w, bv.w);
            #pragma unroll
            for (int mp = 0; mp < 4; mp++)
                #pragma unroll
                for (int j = 0; j < 4; j++)
                    acc2[mp][j] = fma2(ap[mp], bp[j], acc2[mp][j]);
        }
        __syncthreads();
    }

    #pragma unroll
    for (int mp = 0; mp < 4; mp++) {
        float lo[4], hi[4];
        #pragma unroll
        for (int j = 0; j < 4; j++) upk2(acc2[mp][j], lo[j], hi[j]);
        const int r0 = m0 + tm*8 + 2*mp;
        #pragma unroll
        for (int j = 0; j < 4; j++) {
            int c = n0 + tn*4 + j;
            if (c < N) {
                float v0 = lo[j], v1 = hi[j];
                if (bias) { float b = bias[c]; v0 += b; v1 += b; }
                if (act)  { v0 = siluf(v0); v1 = siluf(v1); }
                if (resid) {
                    v0 += resid[(size_t)r0 * ldr + c];
                    v1 += resid[(size_t)(r0+1) * ldr + c];
                }
                Y[(size_t)r0 * ldy + c]     = v0;
                Y[(size_t)(r0+1) * ldy + c] = v1;
            }
        }
    }
}

// ------------- fused edge kernel (triple-chained mma.sync bf16) -----------------
// 128 threads = 4 warps; 4 nodes/block; warp owns a node; 2 groups of 16 edges.
// Layer-1 fourier, layer-2 (530->16) AND coors layer-1 (16->64) on tensor cores.
// D-frag of each stage == A-frag of the next via k-permutation design.
__global__ __launch_bounds__(128, 5) void edge_kernel(
    const float* __restrict__ coors,
    const float* __restrict__ be2,   // 16
    const float* __restrict__ bc1,   // 64
    const float* __restrict__ Wc2,   // 64
    const float* __restrict__ bc2,   // 1
    float* __restrict__ out_coors)   // NG x 3
{
    __shared__ __align__(16) float sA[NPB*EHP];
    __shared__ float sWc2[64];
    __shared__ float sbc1[64];
    __shared__ float sbe2[16];
    __shared__ float sfe[NPB*32*9];
    __shared__ float srel[NPB*32*3];
    __shared__ int   sj[NPB*32];

    const int tid  = threadIdx.x;
    const int w    = tid >> 5;
    const int lane = tid & 31;

    {
        const int g0 = blockIdx.x * NPB;
        for (int i = tid; i < NPB*EHP; i += 128)
            sA[i] = d_A[(size_t)g0*EHP + i];
    }
    if (tid < 64) sWc2[tid] = Wc2[tid];
    if (tid < 64) sbc1[tid] = bc1[tid];
    if (tid < 16) sbe2[tid] = be2[tid];

    const int g = blockIdx.x * NPB + w;
    const int boff = g & ~(NPTS - 1);
    const float cix = coors[g*3+0], ciy = coors[g*3+1], ciz = coors[g*3+2];
    const float bc2v = bc2[0];

    // precompute all 32 edges' fourier features + rel coords (one lane each)
    {
        const int j = d_idx[g*KNN_K + lane];
        sj[w*32 + lane] = j;
        const int r = boff + j;
        float rx = cix - coors[r*3+0];
        float ry = ciy - coors[r*3+1];
        float rz = ciz - coors[r*3+2];
        float d  = rx*rx + ry*ry + rz*rz;
        float* fp = sfe + (w*32 + lane)*9;
        float s, c;
        sincosf(d,        &s, &c); fp[0] = s; fp[4] = c;
        sincosf(d*0.5f,   &s, &c); fp[1] = s; fp[5] = c;
        sincosf(d*0.25f,  &s, &c); fp[2] = s; fp[6] = c;
        sincosf(d*0.125f, &s, &c); fp[3] = s; fp[7] = c;
        fp[8] = d;
        float* rp = srel + (w*32 + lane)*3;
        rp[0] = rx; rp[1] = ry; rp[2] = rz;
    }
    __syncthreads();

    const int q  = lane & 3;          // fragment quad id
    const int E1 = lane >> 2;         // mma row (edge) 0..7
    const int E2 = E1 + 8;
    unsigned long long ms0 = 0ull, ms1 = 0ull;   // colsum partials (t=2q,2q+1),(2q+8,2q+9)
    float cax = 0.f, cay = 0.f, caz = 0.f;

    const float be2a = sbe2[2*q],   be2b = sbe2[2*q+1];
    const float be2c = sbe2[2*q+8], be2d = sbe2[2*q+9];

    #pragma unroll 1
    for (int grp = 0; grp < 2; grp++) {
        const int e0 = grp*16;
        // Fe A-fragment
        unsigned feA0, feA1, feA2, feA3;
        {
            const float* f1 = sfe + (w*32 + e0 + E1)*9;
            const float* f2 = sfe + (w*32 + e0 + E2)*9;
            const int fq = 4*q;
            float a0 = (fq   < 9) ? f1[fq]   : 0.f;
            float a1 = (fq+1 < 9) ? f1[fq+1] : 0.f;
            float a2 = (fq+2 < 9) ? f1[fq+2] : 0.f;
            float a3 = (fq+3 < 9) ? f1[fq+3] : 0.f;
            float b0 = (fq   < 9) ? f2[fq]   : 0.f;
            float b1 = (fq+1 < 9) ? f2[fq+1] : 0.f;
            float b2 = (fq+2 < 9) ? f2[fq+2] : 0.f;
            float b3 = (fq+3 < 9) ? f2[fq+3] : 0.f;
            feA0 = cvtbf2(a0, a1);
            feA1 = cvtbf2(b0, b1);
            feA2 = cvtbf2(a2, a3);
            feA3 = cvtbf2(b2, b3);
        }
        const float* pB1 = d_Bf + (size_t)(boff + sj[w*32 + e0 + E1]) * EHP;
        const float* pB2 = d_Bf + (size_t)(boff + sj[w*32 + e0 + E2]) * EHP;

        float m00=0.f,m01=0.f,m02=0.f,m03=0.f;
        float m10=0.f,m11=0.f,m12=0.f,m13=0.f;

        ulonglong2 bb1 = *(const ulonglong2*)(pB1 + 4*q);
        ulonglong2 bb2 = *(const ulonglong2*)(pB2 + 4*q);

        #pragma unroll 1
        for (int s = 0; s < NSTEP; s++) {
            const int ka = s*16 + 4*q;
            ulonglong2 nb1, nb2;
            if (s < NSTEP-1) {
                nb1 = *(const ulonglong2*)(pB1 + ka + 16);
                nb2 = *(const ulonglong2*)(pB2 + ka + 16);
            }
            const ulonglong2 aa = *(const ulonglong2*)(sA + w*EHP + ka);
            float d00,d01,d02,d03, u00,u01,u02,u03;
            { unsigned long long t = add2(aa.x, bb1.x); upk2(t, d00, d01); }
            { unsigned long long t = add2(aa.x, bb2.x); upk2(t, d02, d03); }
            { unsigned long long t = add2(aa.y, bb1.y); upk2(t, u00, u01); }
            { unsigned long long t = add2(aa.y, bb2.y); upk2(t, u02, u03); }
            const uint4 wf = *(const uint4*)&d_W1ffrag[(s*32 + lane)*4];
            MMA_BF16(d00,d01,d02,d03, feA0,feA1,feA2,feA3, wf.x, wf.y);
            MMA_BF16(u00,u01,u02,u03, feA0,feA1,feA2,feA3, wf.z, wf.w);
            const unsigned a0 = cvtbf2(silu_fast(d00), silu_fast(d01));
            const unsigned a1 = cvtbf2(silu_fast(d02), silu_fast(d03));
            const unsigned a2 = cvtbf2(silu_fast(u00), silu_fast(u01));
            const unsigned a3 = cvtbf2(silu_fast(u02), silu_fast(u03));
            const uint4 bf = *(const uint4*)&d_We2frag[(s*32 + lane)*4];
            MMA_BF16(m00,m01,m02,m03, a0,a1,a2,a3, bf.x, bf.y);
            MMA_BF16(m10,m11,m12,m13, a0,a1,a2,a3, bf.z, bf.w);
            bb1 = nb1; bb2 = nb2;
        }

        // m' = silu(m + be2)   (fp32, in registers)
        const float s00 = siluf(m00 + be2a), s01 = siluf(m01 + be2b);
        const float s02 = siluf(m02 + be2a), s03 = siluf(m03 + be2b);
        const float s10 = siluf(m10 + be2c), s11 = siluf(m11 + be2d);
        const float s12 = siluf(m12 + be2c), s13 = siluf(m13 + be2d);

        // accumulate colsum partials for m_i (rows E1+E2 local)
        ms0 = add2(ms0, add2(pk2(s00, s01), pk2(s02, s03)));
        ms1 = add2(ms1, add2(pk2(s10, s11), pk2(s12, s13)));

        // coors layer-1 on tensor cores: A-frag = m' (D-frag layout == A-frag layout)
        const unsigned am0 = cvtbf2(s00, s01);
        const unsigned am1 = cvtbf2(s02, s03);
        const unsigned am2 = cvtbf2(s10, s11);
        const unsigned am3 = cvtbf2(s12, s13);
        float wE1 = 0.f, wE2 = 0.f;
        #pragma unroll
        for (int nt = 0; nt < 8; nt++) {
            const uint2 wb = d_Wc1frag[nt*32 + lane];
            float h0=0.f,h1=0.f,h2=0.f,h3=0.f;
            MMA_BF16(h0,h1,h2,h3, am0,am1,am2,am3, wb.x, wb.y);
            const float2 bb = *(const float2*)(sbc1 + nt*8 + 2*q);
            const float2 cc = *(const float2*)(sWc2 + nt*8 + 2*q);
            wE1 += silu_fast(h0 + bb.x)*cc.x + silu_fast(h1 + bb.y)*cc.y;
            wE2 += silu_fast(h2 + bb.x)*cc.x + silu_fast(h3 + bb.y)*cc.y;
        }
        // reduce over q-lanes (cols): both edges packed
        unsigned long long wp = pk2(wE1, wE2);
        wp = add2(wp, __shfl_xor_sync(0xffffffffu, wp, 1));
        wp = add2(wp, __shfl_xor_sync(0xffffffffu, wp, 2));
        float we1, we2; upk2(wp, we1, we2);
        we1 += bc2v; we2 += bc2v;
        if (q == 0) {
            const float* r1 = srel + (w*32 + e0 + E1)*3;
            const float* r2 = srel + (w*32 + e0 + E2)*3;
            cax += we1*r1[0] + we2*r2[0];
            cay += we1*r1[1] + we2*r2[1];
            caz += we1*r1[2] + we2*r2[2];
        }
    }

    // m_i: finish colsum across edge-row lanes (same q, different E)
    ms0 = add2(ms0, __shfl_xor_sync(0xffffffffu, ms0, 4));
    ms0 = add2(ms0, __shfl_xor_sync(0xffffffffu, ms0, 8));
    ms0 = add2(ms0, __shfl_xor_sync(0xffffffffu, ms0, 16));
    ms1 = add2(ms1, __shfl_xor_sync(0xffffffffu, ms1, 4));
    ms1 = add2(ms1, __shfl_xor_sync(0xffffffffu, ms1, 8));
    ms1 = add2(ms1, __shfl_xor_sync(0xffffffffu, ms1, 16));
    if (lane < 4) {
        float lo, hi;
        upk2(ms0, lo, hi);
        d_mi[(size_t)g*MDIM + 2*lane    ] = lo;
        d_mi[(size_t)g*MDIM + 2*lane + 1] = hi;
        upk2(ms1, lo, hi);
        d_mi[(size_t)g*MDIM + 2*lane + 8] = lo;
        d_mi[(size_t)g*MDIM + 2*lane + 9] = hi;
    }

    // coords: sum over the 8 E-lane groups (q==0 lanes hold partials)
    cax += __shfl_xor_sync(0xffffffffu, cax, 4);
    cax += __shfl_xor_sync(0xffffffffu, cax, 8);
    cax += __shfl_xor_sync(0xffffffffu, cax, 16);
    cay += __shfl_xor_sync(0xffffffffu, cay, 4);
    cay += __shfl_xor_sync(0xffffffffu, cay, 8);
    cay += __shfl_xor_sync(0xffffffffu, cay, 16);
    caz += __shfl_xor_sync(0xffffffffu, caz, 4);
    caz += __shfl_xor_sync(0xffffffffu, caz, 8);
    caz += __shfl_xor_sync(0xffffffffu, caz, 16);
    if (lane == 0) {
        out_coors[g*3+0] = cax + cix;
        out_coors[g*3+1] = cay + ciy;
        out_coors[g*3+2] = caz + ciz;
    }
}

// build concat(feats, m_i) -> d_nodein
__global__ void nodein_kernel(const float* __restrict__ feats)
{
    int i = blockIdx.x * blockDim.x + threadIdx.x;
    if (i < NG * NODE_IN) {
        int gg = i / NODE_IN, c = i - gg * NODE_IN;
        d_nodein[i] = (c < DIM) ? feats[(size_t)gg*DIM + c]
                                : d_mi[(size_t)gg*MDIM + (c - DIM)];
    }
}

// ------------------------------ launch ----------------------------------------
extern "C" void kernel_launch(void* const* d_in, const int* in_sizes, int n_in,
                              void* d_out, int out_size)
{
    const float* feats = (const float*)d_in[0];
    const float* coors = (const float*)d_in[1];
    const float* We1   = (const float*)d_in[2];
    const float* be1   = (const float*)d_in[3];
    const float* We2   = (const float*)d_in[4];
    const float* be2   = (const float*)d_in[5];
    const float* Wc1   = (const float*)d_in[6];
    const float* bc1   = (const float*)d_in[7];
    const float* Wc2   = (const float*)d_in[8];
    const float* bc2   = (const float*)d_in[9];
    const float* Wn1   = (const float*)d_in[10];
    const float* bn1   = (const float*)d_in[11];
    const float* Wn2   = (const float*)d_in[12];
    const float* bn2   = (const float*)d_in[13];

    float* out_nodes = (float*)d_out;
    float* out_coors = out_nodes + (size_t)NG * DIM;

    float *pA, *pB, *pNI, *pH;
    cudaGetSymbolAddress((void**)&pA,  d_A);
    cudaGetSymbolAddress((void**)&pB,  d_Bf);
    cudaGetSymbolAddress((void**)&pNI, d_nodein);
    cudaGetSymbolAddress((void**)&pH,  d_h);

    // 0. fragment tables
    pad_weights_kernel<<<(NSTEP*32 + 255)/256, 256>>>(We1, We2, Wc1);

    // 1. KNN
    knn_kernel<<<NG, 256>>>(coors);

    // 2. A = feats @ We1[0:128] + be1 ; B = feats @ We1[128:256]   (ld-out = 544)
    {
        dim3 grid((EH + 63) / 64, NG / 128);
        gemm_k<<<grid, 256>>>(feats, DIM, We1,          EH, be1,     nullptr, 0, pA, EHP, NG, EH, DIM, 0);
        gemm_k<<<grid, 256>>>(feats, DIM, We1 + 128*EH, EH, nullptr, nullptr, 0, pB, EHP, NG, EH, DIM, 0);
    }

    // 3. fused edge kernel: m_i + coors_out
    edge_kernel<<<NG / NPB, 128>>>(coors, be2, bc1, Wc2, bc2, out_coors);

    // 4. node MLP
    nodein_kernel<<<(NG*NODE_IN + 255)/256, 256>>>(feats);
    {
        dim3 g1(NODE_H / 64, NG / 128);
        gemm_k<<<g1, 256>>>(pNI, NODE_IN, Wn1, NODE_H, bn1, nullptr, 0, pH, NODE_H, NG, NODE_H, NODE_IN, 1);
        dim3 g2(DIM / 64, NG / 128);
        gemm_k<<<g2, 256>>>(pH, NODE_H, Wn2, DIM, bn2, feats, DIM, out_nodes, DIM, NG, DIM, NODE_H, 0);
    }
}

// round 13
// speedup vs baseline: 3.1281x; 1.1703x over previous
#include <cuda_runtime.h>
#include <cuda_bf16.h>
#include <math.h>

// Problem constants
#define BATCH 2
#define NPTS  4096
#define NG    (BATCH*NPTS)     // 8192 nodes total
#define DIM   128
#define MDIM  16
#define KNN_K 32
#define EH    530              // edge hidden dim (2*265)
#define EHP   544              // padded to 34*16
#define NSTEP 34               // k-tiles of 16
#define NODE_IN 144            // DIM + MDIM
#define NODE_H  256
#define NPB   4                // nodes per edge-kernel block (1 warp each)

// -------------------- scratch (static device globals; no allocation) ----------
__device__ float d_A [NG * EHP];      // feats @ We1[0:128] + be1   (cols 530..543 stay 0)
__device__ float d_Bf[NG * EHP];      // feats @ We1[128:256]       (cols 530..543 stay 0)
__device__ int   d_idx[NG * KNN_K];
__device__ float d_mi [NG * MDIM];
__device__ float d_nodein[NG * NODE_IN];
__device__ float d_h  [NG * NODE_H];
__device__ unsigned d_We2frag[NSTEP * 32 * 4];  // bf16 B-fragments (layer 2)
__device__ unsigned d_W1ffrag[NSTEP * 32 * 4];  // bf16 B-fragments (fourier layer 1)
__device__ uint2    d_Wc1frag[8 * 32];          // bf16 B-fragments (coors layer 1)
// packed-transposed bf16 weights for gemm_mma: [n][k/2] u32 (zero-padded)
__device__ unsigned d_WP0[576 * 64];            // We1[0:128]   -> N=530(576), K=128
__device__ unsigned d_WP1[576 * 64];            // We1[128:256] -> N=530(576), K=128
__device__ unsigned d_WP2[256 * 80];            // Wn1: N=256, K=144 (K2P=80)
__device__ unsigned d_WP3[128 * 128];           // Wn2: N=128, K=256

__device__ __forceinline__ float siluf(float x) {
    return x / (1.0f + __expf(-x));
}
__device__ __forceinline__ float silu_fast(float x) {
    float xh = 0.5f * x;
    float t; asm("tanh.approx.f32 %0, %1;" : "=f"(t) : "f"(xh));
    return fmaf(xh, t, xh);
}

// ---------------- packed f32x2 helpers ------------------------------------------
__device__ __forceinline__ unsigned long long pk2(float lo, float hi) {
    unsigned long long r; asm("mov.b64 %0, {%1,%2};" : "=l"(r) : "f"(lo), "f"(hi)); return r;
}
__device__ __forceinline__ void upk2(unsigned long long v, float &lo, float &hi) {
    asm("mov.b64 {%0,%1}, %2;" : "=f"(lo), "=f"(hi) : "l"(v));
}
__device__ __forceinline__ unsigned long long add2(unsigned long long a,
                                                   unsigned long long b) {
    unsigned long long d;
    asm("add.rn.f32x2 %0, %1, %2;" : "=l"(d) : "l"(a), "l"(b));
    return d;
}
// bf16x2 pack: lo -> d[15:0], hi -> d[31:16]
__device__ __forceinline__ unsigned cvtbf2(float lo, float hi) {
    unsigned r; asm("cvt.rn.bf16x2.f32 %0, %1, %2;" : "=r"(r) : "f"(hi), "f"(lo)); return r;
}

#define MMA_BF16(d0,d1,d2,d3,a0,a1,a2,a3,b0,b1) \
    asm("mma.sync.aligned.m16n8k16.row.col.f32.bf16.bf16.f32 " \
        "{%0,%1,%2,%3},{%4,%5,%6,%7},{%8,%9},{%0,%1,%2,%3};" \
        : "+f"(d0),"+f"(d1),"+f"(d2),"+f"(d3) \
        : "r"(a0),"r"(a1),"r"(a2),"r"(a3),"r"(b0),"r"(b1))

// ---------------------- build packed fragment tables ---------------------------
__global__ void pad_weights_kernel(const float* __restrict__ We1,
                                   const float* __restrict__ We2,
                                   const float* __restrict__ Wc1)
{
    int i = blockIdx.x * blockDim.x + threadIdx.x;   // over NSTEP*32
    if (i < NSTEP * 32) {
        const int s = i >> 5, l = i & 31;
        const int q = l & 3, c0 = l >> 2;
        {   // We2 fragments (layer 2)
            const int k0 = s * 16 + q * 4;
            float v0 = (k0+0 < EH) ? We2[(k0+0)*16 + c0] : 0.f;
            float v1 = (k0+1 < EH) ? We2[(k0+1)*16 + c0] : 0.f;
            float v2 = (k0+2 < EH) ? We2[(k0+2)*16 + c0] : 0.f;
            float v3 = (k0+3 < EH) ? We2[(k0+3)*16 + c0] : 0.f;
            float w0 = (k0+0 < EH) ? We2[(k0+0)*16 + c0+8] : 0.f;
            float w1 = (k0+1 < EH) ? We2[(k0+1)*16 + c0+8] : 0.f;
            float w2 = (k0+2 < EH) ? We2[(k0+2)*16 + c0+8] : 0.f;
            float w3 = (k0+3 < EH) ? We2[(k0+3)*16 + c0+8] : 0.f;
            d_We2frag[i*4+0] = cvtbf2(v0, v1);
            d_We2frag[i*4+1] = cvtbf2(v2, v3);
            d_We2frag[i*4+2] = cvtbf2(w0, w1);
            d_We2frag[i*4+3] = cvtbf2(w2, w3);
        }
        {   // W1f fragments (layer 1)
            const int rk0 = 4*(c0 >> 1) + (c0 & 1);
            const int ka = s*16 + rk0, kb = ka + 2;
            const int f0 = 4*q, f1 = 4*q+1, f2 = 4*q+2, f3 = 4*q+3;
            #define W1F(f,k) (((f) < 9 && (k) < EH) ? We1[(256+(f))*EH + (k)] : 0.f)
            d_W1ffrag[i*4+0] = cvtbf2(W1F(f0,ka), W1F(f1,ka));
            d_W1ffrag[i*4+1] = cvtbf2(W1F(f2,ka), W1F(f3,ka));
            d_W1ffrag[i*4+2] = cvtbf2(W1F(f0,kb), W1F(f1,kb));
            d_W1ffrag[i*4+3] = cvtbf2(W1F(f2,kb), W1F(f3,kb));
            #undef W1F
        }
    }
    if (i < 8 * 32) {   // Wc1 fragments (coors layer 1)
        const int nt = i >> 5, l = i & 31;
        const int q = l & 3, c = l >> 2;
        const int col = nt*8 + c;
        d_Wc1frag[i].x = cvtbf2(Wc1[(2*q  )*64 + col], Wc1[(2*q+1)*64 + col]);
        d_Wc1frag[i].y = cvtbf2(Wc1[(2*q+8)*64 + col], Wc1[(2*q+9)*64 + col]);
    }
}

// pack-transpose fp32 W[K][N] (row stride ldw) -> u32 WP[NP][K2P] of bf16 pairs
__global__ void pack_w_kernel(const float* __restrict__ W, int ldw,
                              unsigned* __restrict__ WP,
                              int K, int N, int NP, int K2P)
{
    int i = blockIdx.x * blockDim.x + threadIdx.x;
    if (i < NP * K2P) {
        int n = i / K2P, j = i - n * K2P;
        float lo = (n < N && 2*j   < K) ? W[(size_t)(2*j  )*ldw + n] : 0.f;
        float hi = (n < N && 2*j+1 < K) ? W[(size_t)(2*j+1)*ldw + n] : 0.f;
        WP[i] = cvtbf2(lo, hi);
    }
}

// ------------------------------ KNN -------------------------------------------
__global__ __launch_bounds__(256) void knn_kernel(const float* __restrict__ coors)
{
    __shared__ unsigned long long keys[256];
    __shared__ unsigned long long swin;
    const int tid = threadIdx.x;
    const int g = blockIdx.x;
    const int boff = g & ~(NPTS - 1);

    const float cix = coors[g*3+0], ciy = coors[g*3+1], ciz = coors[g*3+2];

    float dv[16];
    #pragma unroll
    for (int s = 0; s < 16; s++) {
        const int j = tid + s*256;
        const int r = boff + j;
        float dx = cix - coors[r*3+0];
        float dy = ciy - coors[r*3+1];
        float dz = ciz - coors[r*3+2];
        dv[s] = dx*dx + dy*dy + dz*dz;
    }
    unsigned long long lb = 0xFFFFFFFFFFFFFFFFull;
    #pragma unroll
    for (int s = 0; s < 16; s++) {
        unsigned long long key =
            ((unsigned long long)__float_as_uint(dv[s]) << 32) | (unsigned)(tid + s*256);
        if (key < lb) lb = key;
    }

    for (int k = 0; k < KNN_K; k++) {
        keys[tid] = lb;
        __syncthreads();
        if (tid < 32) {
            unsigned long long v = keys[tid];
            #pragma unroll
            for (int o = 1; o < 8; o++) {
                unsigned long long t = keys[tid + o*32];
                if (t < v) v = t;
            }
            #pragma unroll
            for (int off = 16; off; off >>= 1) {
                unsigned long long o = __shfl_xor_sync(0xffffffffu, v, off);
                if (o < v) v = o;
            }
            if (tid == 0) {
                swin = v;
                d_idx[g*KNN_K + k] = (int)(v & 0xFFFFFFFFull);
            }
        }
        __syncthreads();
        const int wj = (int)(swin & 0xFFFFFFFFull);
        if ((wj & 255) == tid) {
            dv[wj >> 8] = __int_as_float(0x7F800000);
            lb = 0xFFFFFFFFFFFFFFFFull;
            #pragma unroll
            for (int s = 0; s < 16; s++) {
                unsigned long long key =
                    ((unsigned long long)__float_as_uint(dv[s]) << 32) | (unsigned)(tid + s*256);
                if (key < lb) lb = key;
            }
        }
    }
}

// ------------------------ tensor-core GEMM (bf16 mma, fp32 accum) ---------------
// Y[m][n] = act( X[m][:]@W + bias ) + resid.  W pre-packed as WP[n][K2P] bf16-pairs.
// BM=128, BN=64, BK=32; 8 warps, warp tile 32x32.
__global__ __launch_bounds__(256) void gemm_mma(
    const float* __restrict__ X, int ldx,
    const unsigned* __restrict__ WP, int K2P,
    const float* __restrict__ bias,
    const float* __restrict__ resid, int ldr,
    float* __restrict__ Y, int ldy,
    int M, int N, int K, int act)
{
    __shared__ unsigned A32[128*20];
    __shared__ unsigned B32[64*20];
    const int tid  = threadIdx.x;
    const int w    = tid >> 5;
    const int lane = tid & 31;
    const int r = lane >> 2, q = lane & 3;
    const int warpM = (w & 3) * 32, warpN = (w >> 2) * 32;
    const int m0 = blockIdx.y * 128, n0 = blockIdx.x * 64;

    float acc[2][4][4];
    #pragma unroll
    for (int mt = 0; mt < 2; mt++)
        #pragma unroll
        for (int nt = 0; nt < 4; nt++)
            #pragma unroll
            for (int e = 0; e < 4; e++) acc[mt][nt][e] = 0.f;

    for (int k0 = 0; k0 < K; k0 += 32) {
        // X tile 128x32 fp32 -> bf16 pairs
        #pragma unroll
        for (int i = 0; i < 4; i++) {
            int idx = tid + i*256;
            int m = idx >> 3, j4 = idx & 7;
            int kk = k0 + j4*4;
            float4 xv;
            if (kk < K) xv = *(const float4*)&X[(size_t)(m0 + m) * ldx + kk];
            else        xv = make_float4(0.f, 0.f, 0.f, 0.f);
            A32[m*20 + j4*2    ] = cvtbf2(xv.x, xv.y);
            A32[m*20 + j4*2 + 1] = cvtbf2(xv.z, xv.w);
        }
        // W tile (pre-packed)
        #pragma unroll
        for (int i = 0; i < 4; i++) {
            int idx = tid + i*256;
            int n = idx >> 4, j = idx & 15;
            B32[n*20 + j] = WP[(size_t)(n0 + n) * K2P + (k0 >> 1) + j];
        }
        __syncthreads();
        #pragma unroll
        for (int ks = 0; ks < 2; ks++) {
            unsigned bfr[4][2];
            #pragma unroll
            for (int nt = 0; nt < 4; nt++) {
                bfr[nt][0] = B32[(warpN + nt*8 + r)*20 + ks*8 + q];
                bfr[nt][1] = B32[(warpN + nt*8 + r)*20 + ks*8 + q + 4];
            }
            #pragma unroll
            for (int mt = 0; mt < 2; mt++) {
                const int rowb = (warpM + mt*16 + r)*20 + ks*8 + q;
                unsigned a0 = A32[rowb];
                unsigned a1 = A32[rowb + 8*20];
                unsigned a2 = A32[rowb + 4];
                unsigned a3 = A32[rowb + 8*20 + 4];
                #pragma unroll
                for (int nt = 0; nt < 4; nt++)
                    MMA_BF16(acc[mt][nt][0], acc[mt][nt][1], acc[mt][nt][2], acc[mt][nt][3],
                             a0, a1, a2, a3, bfr[nt][0], bfr[nt][1]);
            }
        }
        __syncthreads();
    }

    // epilogue
    #pragma unroll
    for (int mt = 0; mt < 2; mt++) {
        #pragma unroll
        for (int nt = 0; nt < 4; nt++) {
            const int row0 = m0 + warpM + mt*16 + r;
            const int c0 = n0 + warpN + nt*8 + 2*q;
            #pragma unroll
            for (int e = 0; e < 2; e++) {
                int c = c0 + e;
                if (c < N) {
                    float v0 = acc[mt][nt][e];      // (row0, c)
                    float v1 = acc[mt][nt][e + 2];  // (row0+8, c)
                    if (bias) { float b = bias[c]; v0 += b; v1 += b; }
                    if (act)  { v0 = siluf(v0); v1 = siluf(v1); }
                    if (resid) {
                        v0 += resid[(size_t)row0 * ldr + c];
                        v1 += resid[(size_t)(row0 + 8) * ldr + c];
                    }
                    Y[(size_t)row0 * ldy + c]     = v0;
                    Y[(size_t)(row0 + 8) * ldy + c] = v1;
                }
            }
        }
    }
}

// ------------- fused edge kernel (triple-chained mma.sync bf16) -----------------
__global__ __launch_bounds__(128, 5) void edge_kernel(
    const float* __restrict__ coors,
    const float* __restrict__ be2,   // 16
    const float* __restrict__ bc1,   // 64
    const float* __restrict__ Wc2,   // 64
    const float* __restrict__ bc2,   // 1
    float* __restrict__ out_coors)   // NG x 3
{
    __shared__ __align__(16) float sA[NPB*EHP];
    __shared__ float sWc2[64];
    __shared__ float sbc1[64];
    __shared__ float sbe2[16];
    __shared__ float sfe[NPB*32*9];
    __shared__ float srel[NPB*32*3];
    __shared__ int   sj[NPB*32];

    const int tid  = threadIdx.x;
    const int w    = tid >> 5;
    const int lane = tid & 31;

    {
        const int g0 = blockIdx.x * NPB;
        for (int i = tid; i < NPB*EHP; i += 128)
            sA[i] = d_A[(size_t)g0*EHP + i];
    }
    if (tid < 64) sWc2[tid] = Wc2[tid];
    if (tid < 64) sbc1[tid] = bc1[tid];
    if (tid < 16) sbe2[tid] = be2[tid];

    const int g = blockIdx.x * NPB + w;
    const int boff = g & ~(NPTS - 1);
    const float cix = coors[g*3+0], ciy = coors[g*3+1], ciz = coors[g*3+2];
    const float bc2v = bc2[0];

    {
        const int j = d_idx[g*KNN_K + lane];
        sj[w*32 + lane] = j;
        const int r = boff + j;
        float rx = cix - coors[r*3+0];
        float ry = ciy - coors[r*3+1];
        float rz = ciz - coors[r*3+2];
        float d  = rx*rx + ry*ry + rz*rz;
        float* fp = sfe + (w*32 + lane)*9;
        float s, c;
        sincosf(d,        &s, &c); fp[0] = s; fp[4] = c;
        sincosf(d*0.5f,   &s, &c); fp[1] = s; fp[5] = c;
        sincosf(d*0.25f,  &s, &c); fp[2] = s; fp[6] = c;
        sincosf(d*0.125f, &s, &c); fp[3] = s; fp[7] = c;
        fp[8] = d;
        float* rp = srel + (w*32 + lane)*3;
        rp[0] = rx; rp[1] = ry; rp[2] = rz;
    }
    __syncthreads();

    const int q  = lane & 3;
    const int E1 = lane >> 2;
    const int E2 = E1 + 8;
    unsigned long long ms0 = 0ull, ms1 = 0ull;
    float cax = 0.f, cay = 0.f, caz = 0.f;

    const float be2a = sbe2[2*q],   be2b = sbe2[2*q+1];
    const float be2c = sbe2[2*q+8], be2d = sbe2[2*q+9];

    #pragma unroll 1
    for (int grp = 0; grp < 2; grp++) {
        const int e0 = grp*16;
        unsigned feA0, feA1, feA2, feA3;
        {
            const float* f1 = sfe + (w*32 + e0 + E1)*9;
            const float* f2 = sfe + (w*32 + e0 + E2)*9;
            const int fq = 4*q;
            float a0 = (fq   < 9) ? f1[fq]   : 0.f;
            float a1 = (fq+1 < 9) ? f1[fq+1] : 0.f;
            float a2 = (fq+2 < 9) ? f1[fq+2] : 0.f;
            float a3 = (fq+3 < 9) ? f1[fq+3] : 0.f;
            float b0 = (fq   < 9) ? f2[fq]   : 0.f;
            float b1 = (fq+1 < 9) ? f2[fq+1] : 0.f;
            float b2 = (fq+2 < 9) ? f2[fq+2] : 0.f;
            float b3 = (fq+3 < 9) ? f2[fq+3] : 0.f;
            feA0 = cvtbf2(a0, a1);
            feA1 = cvtbf2(b0, b1);
            feA2 = cvtbf2(a2, a3);
            feA3 = cvtbf2(b2, b3);
        }
        const float* pB1 = d_Bf + (size_t)(boff + sj[w*32 + e0 + E1]) * EHP;
        const float* pB2 = d_Bf + (size_t)(boff + sj[w*32 + e0 + E2]) * EHP;

        float m00=0.f,m01=0.f,m02=0.f,m03=0.f;
        float m10=0.f,m11=0.f,m12=0.f,m13=0.f;

        ulonglong2 bb1 = *(const ulonglong2*)(pB1 + 4*q);
        ulonglong2 bb2 = *(const ulonglong2*)(pB2 + 4*q);

        #pragma unroll 1
        for (int s = 0; s < NSTEP; s++) {
            const int ka = s*16 + 4*q;
            ulonglong2 nb1, nb2;
            if (s < NSTEP-1) {
                nb1 = *(const ulonglong2*)(pB1 + ka + 16);
                nb2 = *(const ulonglong2*)(pB2 + ka + 16);
            }
            const ulonglong2 aa = *(const ulonglong2*)(sA + w*EHP + ka);
            float d00,d01,d02,d03, u00,u01,u02,u03;
            { unsigned long long t = add2(aa.x, bb1.x); upk2(t, d00, d01); }
            { unsigned long long t = add2(aa.x, bb2.x); upk2(t, d02, d03); }
            { unsigned long long t = add2(aa.y, bb1.y); upk2(t, u00, u01); }
            { unsigned long long t = add2(aa.y, bb2.y); upk2(t, u02, u03); }
            const uint4 wf = *(const uint4*)&d_W1ffrag[(s*32 + lane)*4];
            MMA_BF16(d00,d01,d02,d03, feA0,feA1,feA2,feA3, wf.x, wf.y);
            MMA_BF16(u00,u01,u02,u03, feA0,feA1,feA2,feA3, wf.z, wf.w);
            const unsigned a0 = cvtbf2(silu_fast(d00), silu_fast(d01));
            const unsigned a1 = cvtbf2(silu_fast(d02), silu_fast(d03));
            const unsigned a2 = cvtbf2(silu_fast(u00), silu_fast(u01));
            const unsigned a3 = cvtbf2(silu_fast(u02), silu_fast(u03));
            const uint4 bf = *(const uint4*)&d_We2frag[(s*32 + lane)*4];
            MMA_BF16(m00,m01,m02,m03, a0,a1,a2,a3, bf.x, bf.y);
            MMA_BF16(m10,m11,m12,m13, a0,a1,a2,a3, bf.z, bf.w);
            bb1 = nb1; bb2 = nb2;
        }

        const float s00 = siluf(m00 + be2a), s01 = siluf(m01 + be2b);
        const float s02 = siluf(m02 + be2a), s03 = siluf(m03 + be2b);
        const float s10 = siluf(m10 + be2c), s11 = siluf(m11 + be2d);
        const float s12 = siluf(m12 + be2c), s13 = siluf(m13 + be2d);

        ms0 = add2(ms0, add2(pk2(s00, s01), pk2(s02, s03)));
        ms1 = add2(ms1, add2(pk2(s10, s11), pk2(s12, s13)));

        const unsigned am0 = cvtbf2(s00, s01);
        const unsigned am1 = cvtbf2(s02, s03);
        const unsigned am2 = cvtbf2(s10, s11);
        const unsigned am3 = cvtbf2(s12, s13);
        float wE1 = 0.f, wE2 = 0.f;
        #pragma unroll
        for (int nt = 0; nt < 8; nt++) {
            const uint2 wb = d_Wc1frag[nt*32 + lane];
            float h0=0.f,h1=0.f,h2=0.f,h3=0.f;
            MMA_BF16(h0,h1,h2,h3, am0,am1,am2,am3, wb.x, wb.y);
            const float2 bb = *(const float2*)(sbc1 + nt*8 + 2*q);
            const float2 cc = *(const float2*)(sWc2 + nt*8 + 2*q);
            wE1 += silu_fast(h0 + bb.x)*cc.x + silu_fast(h1 + bb.y)*cc.y;
            wE2 += silu_fast(h2 + bb.x)*cc.x + silu_fast(h3 + bb.y)*cc.y;
        }
        unsigned long long wp = pk2(wE1, wE2);
        wp = add2(wp, __shfl_xor_sync(0xffffffffu, wp, 1));
        wp = add2(wp, __shfl_xor_sync(0xffffffffu, wp, 2));
        float we1, we2; upk2(wp, we1, we2);
        we1 += bc2v; we2 += bc2v;
        if (q == 0) {
            const float* r1 = srel + (w*32 + e0 + E1)*3;
            const float* r2 = srel + (w*32 + e0 + E2)*3;
            cax += we1*r1[0] + we2*r2[0];
            cay += we1*r1[1] + we2*r2[1];
            caz += we1*r1[2] + we2*r2[2];
        }
    }

    ms0 = add2(ms0, __shfl_xor_sync(0xffffffffu, ms0, 4));
    ms0 = add2(ms0, __shfl_xor_sync(0xffffffffu, ms0, 8));
    ms0 = add2(ms0, __shfl_xor_sync(0xffffffffu, ms0, 16));
    ms1 = add2(ms1, __shfl_xor_sync(0xffffffffu, ms1, 4));
    ms1 = add2(ms1, __shfl_xor_sync(0xffffffffu, ms1, 8));
    ms1 = add2(ms1, __shfl_xor_sync(0xffffffffu, ms1, 16));
    if (lane < 4) {
        float lo, hi;
        upk2(ms0, lo, hi);
        d_mi[(size_t)g*MDIM + 2*lane    ] = lo;
        d_mi[(size_t)g*MDIM + 2*lane + 1] = hi;
        upk2(ms1, lo, hi);
        d_mi[(size_t)g*MDIM + 2*lane + 8] = lo;
        d_mi[(size_t)g*MDIM + 2*lane + 9] = hi;
    }

    cax += __shfl_xor_sync(0xffffffffu, cax, 4);
    cax += __shfl_xor_sync(0xffffffffu, cax, 8);
    cax += __shfl_xor_sync(0xffffffffu, cax, 16);
    cay += __shfl_xor_sync(0xffffffffu, cay, 4);
    cay += __shfl_xor_sync(0xffffffffu, cay, 8);
    cay += __shfl_xor_sync(0xffffffffu, cay, 16);
    caz += __shfl_xor_sync(0xffffffffu, caz, 4);
    caz += __shfl_xor_sync(0xffffffffu, caz, 8);
    caz += __shfl_xor_sync(0xffffffffu, caz, 16);
    if (lane == 0) {
        out_coors[g*3+0] = cax + cix;
        out_coors[g*3+1] = cay + ciy;
        out_coors[g*3+2] = caz + ciz;
    }
}

// build concat(feats, m_i) -> d_nodein
__global__ void nodein_kernel(const float* __restrict__ feats)
{
    int i = blockIdx.x * blockDim.x + threadIdx.x;
    if (i < NG * NODE_IN) {
        int gg = i / NODE_IN, c = i - gg * NODE_IN;
        d_nodein[i] = (c < DIM) ? feats[(size_t)gg*DIM + c]
                                : d_mi[(size_t)gg*MDIM + (c - DIM)];
    }
}

// ------------------------------ launch ----------------------------------------
extern "C" void kernel_launch(void* const* d_in, const int* in_sizes, int n_in,
                              void* d_out, int out_size)
{
    const float* feats = (const float*)d_in[0];
    const float* coors = (const float*)d_in[1];
    const float* We1   = (const float*)d_in[2];
    const float* be1   = (const float*)d_in[3];
    const float* We2   = (const float*)d_in[4];
    const float* be2   = (const float*)d_in[5];
    const float* Wc1   = (const float*)d_in[6];
    const float* bc1   = (const float*)d_in[7];
    const float* Wc2   = (const float*)d_in[8];
    const float* bc2   = (const float*)d_in[9];
    const float* Wn1   = (const float*)d_in[10];
    const float* bn1   = (const float*)d_in[11];
    const float* Wn2   = (const float*)d_in[12];
    const float* bn2   = (const float*)d_in[13];

    float* out_nodes = (float*)d_out;
    float* out_coors = out_nodes + (size_t)NG * DIM;

    float *pA, *pB, *pNI, *pH;
    unsigned *pW0, *pW1, *pW2, *pW3;
    cudaGetSymbolAddress((void**)&pA,  d_A);
    cudaGetSymbolAddress((void**)&pB,  d_Bf);
    cudaGetSymbolAddress((void**)&pNI, d_nodein);
    cudaGetSymbolAddress((void**)&pH,  d_h);
    cudaGetSymbolAddress((void**)&pW0, d_WP0);
    cudaGetSymbolAddress((void**)&pW1, d_WP1);
    cudaGetSymbolAddress((void**)&pW2, d_WP2);
    cudaGetSymbolAddress((void**)&pW3, d_WP3);

    // 0. fragment + packed-weight tables
    pad_weights_kernel<<<(NSTEP*32 + 255)/256, 256>>>(We1, We2, Wc1);
    pack_w_kernel<<<(576*64 + 255)/256, 256>>>(We1,          EH,     pW0, DIM,     EH,     576, 64);
    pack_w_kernel<<<(576*64 + 255)/256, 256>>>(We1 + 128*EH, EH,     pW1, DIM,     EH,     576, 64);
    pack_w_kernel<<<(256*80 + 255)/256, 256>>>(Wn1,          NODE_H, pW2, NODE_IN, NODE_H, 256, 80);
    pack_w_kernel<<<(128*128+ 255)/256, 256>>>(Wn2,          DIM,    pW3, NODE_H,  DIM,    128, 128);

    // 1. KNN
    knn_kernel<<<NG, 256>>>(coors);

    // 2. A = feats @ We1[0:128] + be1 ; B = feats @ We1[128:256]   (ld-out = 544)
    {
        dim3 grid((EH + 63) / 64, NG / 128);
        gemm_mma<<<grid, 256>>>(feats, DIM, pW0, 64, be1,     nullptr, 0, pA, EHP, NG, EH, DIM, 0);
        gemm_mma<<<grid, 256>>>(feats, DIM, pW1, 64, nullptr, nullptr, 0, pB, EHP, NG, EH, DIM, 0);
    }

    // 3. fused edge kernel: m_i + coors_out
    edge_kernel<<<NG / NPB, 128>>>(coors, be2, bc1, Wc2, bc2, out_coors);

    // 4. node MLP
    nodein_kernel<<<(NG*NODE_IN + 255)/256, 256>>>(feats);
    {
        dim3 g1(NODE_H / 64, NG / 128);
        gemm_mma<<<g1, 256>>>(pNI, NODE_IN, pW2, 80, bn1, nullptr, 0, pH, NODE_H, NG, NODE_H, NODE_IN, 1);
        dim3 g2(DIM / 64, NG / 128);
        gemm_mma<<<g2, 256>>>(pH, NODE_H, pW3, 128, bn2, feats, DIM, out_nodes, DIM, NG, DIM, NODE_H, 0);
    }
}